// round 4
// baseline (speedup 1.0000x reference)
#include <cuda_runtime.h>

#define N_NODES_C 100000
#define N_EDGES_C 50000
#define NNZ_CAP   1600000
#define F1 128
#define F2 16

// ---------------- static scratch (no cudaMalloc anywhere) ----------------
__device__ int   g_idx64;
__device__ int   g_ncnt[N_NODES_C];
__device__ int   g_ecnt[N_EDGES_C];
__device__ int   g_noff[N_NODES_C + 1];
__device__ int   g_eoff[N_EDGES_C + 1];
__device__ int   g_ncur[N_NODES_C];
__device__ int   g_ecur[N_EDGES_C];
__device__ float g_dinv[N_NODES_C];
__device__ float g_binv[N_EDGES_C];
__device__ int   g_e_members[NNZ_CAP];         // node ids grouped by edge
__device__ int   g_n_members[NNZ_CAP];         // edge ids grouped by node
__device__ __align__(16) float g_xw[(size_t)N_NODES_C * F1];
__device__ __align__(16) float g_efeat[(size_t)N_EDGES_C * F1];
__device__ __align__(16) float g_hw[(size_t)N_NODES_C * F2];
__device__ __align__(16) float g_efeat2[(size_t)N_EDGES_C * F2];

__device__ __forceinline__ int load_idx(const void* p, int i, int is64) {
    return is64 ? (int)((const long long*)p)[i] : ((const int*)p)[i];
}

// ---------------- zero counters + detect index dtype (fused) ----------------
__global__ void zero_detect_kernel(const void* ni, int nnz) {
    __shared__ int bad_s;
    int i = blockIdx.x * blockDim.x + threadIdx.x;
    if (i < N_NODES_C) g_ncnt[i] = 0;
    if (i < N_EDGES_C) g_ecnt[i] = 0;
    if (blockIdx.x == 0) {
        if (threadIdx.x == 0) bad_s = 0;
        __syncthreads();
        int k = nnz < 64 ? nnz : 64;
        if ((int)threadIdx.x < k) {
            long long v = ((const long long*)ni)[threadIdx.x];
            if (v < 0 || v >= (1LL << 31)) atomicOr(&bad_s, 1);
        }
        __syncthreads();
        if (threadIdx.x == 0) g_idx64 = bad_s ? 0 : 1;
    }
}

// ---------------- histogram ----------------
__global__ void hist_kernel(const void* ni, const void* ei, int nnz) {
    int i = blockIdx.x * blockDim.x + threadIdx.x;
    if (i >= nnz) return;
    int is64 = g_idx64;
    atomicAdd(&g_ncnt[load_idx(ni, i, is64)], 1);
    atomicAdd(&g_ecnt[load_idx(ei, i, is64)], 1);
}

// ---------------- fused scan: block 0 = edges, block 1 = nodes ----------------
// Chunked 1024-thread scan; writeback also produces off, cur, inv — and off[n].
__global__ __launch_bounds__(1024) void scan_fused_kernel() {
    __shared__ int s[1024];
    const int tid = threadIdx.x;
    const bool edges = (blockIdx.x == 0);
    const int n   = edges ? N_EDGES_C : N_NODES_C;
    int*   cnt = edges ? g_ecnt : g_ncnt;
    int*   off = edges ? g_eoff : g_noff;
    int*   cur = edges ? g_ecur : g_ncur;
    float* inv = edges ? g_binv : g_dinv;
    const int chunk = (n + 1023) >> 10;
    int beg = tid * chunk;
    int end = beg + chunk < n ? beg + chunk : n;
    int sum = 0;
    for (int i = beg; i < end; i++) sum += cnt[i];
    s[tid] = sum;
    __syncthreads();
    for (int d = 1; d < 1024; d <<= 1) {
        int t = (tid >= d) ? s[tid - d] : 0;
        __syncthreads();
        s[tid] += t;
        __syncthreads();
    }
    int run = s[tid] - sum;             // exclusive prefix at chunk start
    for (int i = beg; i < end; i++) {
        int c = cnt[i];
        off[i] = run;
        cur[i] = run;
        inv[i] = c > 0 ? 1.f / (float)c : 0.f;
        run += c;
    }
    if (tid == 1023) off[n] = s[1023];  // grand total
}

// ---------------- fill CSR member lists ----------------
__global__ void fill_kernel(const void* ni, const void* ei, int nnz) {
    int i = blockIdx.x * blockDim.x + threadIdx.x;
    if (i >= nnz) return;
    int is64 = g_idx64;
    int n = load_idx(ni, i, is64);
    int e = load_idx(ei, i, is64);
    g_e_members[atomicAdd(&g_ecur[e], 1)] = n;
    g_n_members[atomicAdd(&g_ncur[n], 1)] = e;
}

// ---------------- GEMM1: tensor-core tf32 (3-pass compensated) ----------------
__device__ __forceinline__ void split_tf32(float x, unsigned& hi, unsigned& lo) {
    asm("cvt.rna.tf32.f32 %0, %1;" : "=r"(hi) : "f"(x));
    float r = x - __uint_as_float(hi);
    asm("cvt.rna.tf32.f32 %0, %1;" : "=r"(lo) : "f"(r));
}

__device__ __forceinline__ void mma_tf32(float* c, unsigned a0, unsigned a1,
                                         unsigned a2, unsigned a3,
                                         unsigned b0, unsigned b1) {
    asm("mma.sync.aligned.m16n8k8.row.col.f32.tf32.tf32.f32 "
        "{%0,%1,%2,%3}, {%4,%5,%6,%7}, {%8,%9}, {%0,%1,%2,%3};"
        : "+f"(c[0]), "+f"(c[1]), "+f"(c[2]), "+f"(c[3])
        : "r"(a0), "r"(a1), "r"(a2), "r"(a3), "r"(b0), "r"(b1));
}

__global__ __launch_bounds__(512) void gemm1_tf32(const float* __restrict__ A,
                                                  const float* __restrict__ W, int M) {
    __shared__ unsigned Ah[128][20], Al[128][20];
    __shared__ unsigned Bh[16][132], Bl[16][132];
    const int tid  = threadIdx.x;
    const int wid  = tid >> 5, lane = tid & 31;
    const int g = lane >> 2, t = lane & 3;
    const int wm = (wid >> 2) * 32;
    const int wn = (wid & 3) * 32;
    const int mbase = blockIdx.x * 128;

    float acc[2][4][4];
#pragma unroll
    for (int a = 0; a < 2; a++)
#pragma unroll
        for (int b = 0; b < 4; b++)
#pragma unroll
            for (int c = 0; c < 4; c++) acc[a][b][c] = 0.f;

    const int ar  = tid >> 2;
    const int ac4 = tid & 3;
    const int br  = tid >> 5;
    const int bc4 = tid & 31;
    const bool avalid = (mbase + ar) < M;
    const float* Arow = A + (size_t)(mbase + ar) * 128;

    for (int kc = 0; kc < 128; kc += 16) {
        float4 av = avalid ? *(const float4*)(Arow + kc + ac4 * 4)
                           : make_float4(0.f, 0.f, 0.f, 0.f);
        float4 bv = *(const float4*)(W + (size_t)(kc + br) * 128 + bc4 * 4);
        unsigned h, l;
        split_tf32(av.x, h, l); Ah[ar][ac4 * 4 + 0] = h; Al[ar][ac4 * 4 + 0] = l;
        split_tf32(av.y, h, l); Ah[ar][ac4 * 4 + 1] = h; Al[ar][ac4 * 4 + 1] = l;
        split_tf32(av.z, h, l); Ah[ar][ac4 * 4 + 2] = h; Al[ar][ac4 * 4 + 2] = l;
        split_tf32(av.w, h, l); Ah[ar][ac4 * 4 + 3] = h; Al[ar][ac4 * 4 + 3] = l;
        split_tf32(bv.x, h, l); Bh[br][bc4 * 4 + 0] = h; Bl[br][bc4 * 4 + 0] = l;
        split_tf32(bv.y, h, l); Bh[br][bc4 * 4 + 1] = h; Bl[br][bc4 * 4 + 1] = l;
        split_tf32(bv.z, h, l); Bh[br][bc4 * 4 + 2] = h; Bl[br][bc4 * 4 + 2] = l;
        split_tf32(bv.w, h, l); Bh[br][bc4 * 4 + 3] = h; Bl[br][bc4 * 4 + 3] = l;
        __syncthreads();

#pragma unroll
        for (int ks = 0; ks < 2; ks++) {
            const int k0 = ks * 8;
            unsigned bh[4][2], bl[4][2];
#pragma unroll
            for (int nt = 0; nt < 4; nt++) {
                int cn = wn + nt * 8 + g;
                bh[nt][0] = Bh[k0 + t][cn];
                bh[nt][1] = Bh[k0 + t + 4][cn];
                bl[nt][0] = Bl[k0 + t][cn];
                bl[nt][1] = Bl[k0 + t + 4][cn];
            }
#pragma unroll
            for (int mt = 0; mt < 2; mt++) {
                const int rm = wm + mt * 16;
                unsigned ah0 = Ah[rm + g][k0 + t];
                unsigned ah1 = Ah[rm + g + 8][k0 + t];
                unsigned ah2 = Ah[rm + g][k0 + t + 4];
                unsigned ah3 = Ah[rm + g + 8][k0 + t + 4];
                unsigned al0 = Al[rm + g][k0 + t];
                unsigned al1 = Al[rm + g + 8][k0 + t];
                unsigned al2 = Al[rm + g][k0 + t + 4];
                unsigned al3 = Al[rm + g + 8][k0 + t + 4];
#pragma unroll
                for (int nt = 0; nt < 4; nt++) {
                    mma_tf32(acc[mt][nt], ah0, ah1, ah2, ah3, bh[nt][0], bh[nt][1]);
                    mma_tf32(acc[mt][nt], ah0, ah1, ah2, ah3, bl[nt][0], bl[nt][1]);
                    mma_tf32(acc[mt][nt], al0, al1, al2, al3, bh[nt][0], bh[nt][1]);
                }
            }
        }
        __syncthreads();
    }

#pragma unroll
    for (int mt = 0; mt < 2; mt++) {
#pragma unroll
        for (int nt = 0; nt < 4; nt++) {
            int row = mbase + wm + mt * 16 + g;
            int col = wn + nt * 8 + 2 * t;
            if (row < M)
                *(float2*)&g_xw[(size_t)row * 128 + col] =
                    make_float2(acc[mt][nt][0], acc[mt][nt][1]);
            if (row + 8 < M)
                *(float2*)&g_xw[(size_t)(row + 8) * 128 + col] =
                    make_float2(acc[mt][nt][2], acc[mt][nt][3]);
        }
    }
}

// ---------------- gather-reduce F=128 (warp per row), plain ----------------
__global__ __launch_bounds__(256) void gather128(const float* __restrict__ src,
                                                 float* __restrict__ dst,
                                                 const int* __restrict__ mem,
                                                 const int* __restrict__ off,
                                                 const float* __restrict__ inv,
                                                 int nrows) {
    int w = (blockIdx.x * blockDim.x + threadIdx.x) >> 5;
    int lane = threadIdx.x & 31;
    if (w >= nrows) return;
    int beg = off[w], end = off[w + 1];
    float4 a0 = make_float4(0.f, 0.f, 0.f, 0.f);
    float4 a1 = make_float4(0.f, 0.f, 0.f, 0.f);
    int j = beg;
    for (; j + 3 < end; j += 4) {
        int m0 = mem[j], m1 = mem[j + 1], m2 = mem[j + 2], m3 = mem[j + 3];
        float4 v0 = *(const float4*)&src[(size_t)m0 * F1 + lane * 4];
        float4 v1 = *(const float4*)&src[(size_t)m1 * F1 + lane * 4];
        float4 v2 = *(const float4*)&src[(size_t)m2 * F1 + lane * 4];
        float4 v3 = *(const float4*)&src[(size_t)m3 * F1 + lane * 4];
        a0.x += v0.x; a0.y += v0.y; a0.z += v0.z; a0.w += v0.w;
        a1.x += v1.x; a1.y += v1.y; a1.z += v1.z; a1.w += v1.w;
        a0.x += v2.x; a0.y += v2.y; a0.z += v2.z; a0.w += v2.w;
        a1.x += v3.x; a1.y += v3.y; a1.z += v3.z; a1.w += v3.w;
    }
    for (; j < end; j++) {
        float4 v0 = *(const float4*)&src[(size_t)mem[j] * F1 + lane * 4];
        a0.x += v0.x; a0.y += v0.y; a0.z += v0.z; a0.w += v0.w;
    }
    float s = inv[w];
    float4 r = make_float4((a0.x + a1.x) * s, (a0.y + a1.y) * s,
                           (a0.z + a1.z) * s, (a0.w + a1.w) * s);
    *(float4*)&dst[(size_t)w * F1 + lane * 4] = r;
}

// ------- gather-reduce F=128 + bias + relu + fused [128x16] W2 multiply -------
__global__ __launch_bounds__(256) void gather128_w2(const float* __restrict__ src,
                                                    const int* __restrict__ mem,
                                                    const int* __restrict__ off,
                                                    const float* __restrict__ inv,
                                                    const float* __restrict__ bias,
                                                    const float* __restrict__ W2,
                                                    float* __restrict__ hw, int nrows) {
    __shared__ float W2s[128][17];
    __shared__ float hs[8][128];
    const int tid = threadIdx.x;
    for (int i = tid; i < 128 * 16; i += 256) W2s[i >> 4][i & 15] = W2[i];
    __syncthreads();

    int w = (blockIdx.x * blockDim.x + tid) >> 5;
    int lane = tid & 31, wl = tid >> 5;
    if (w >= nrows) return;
    int beg = off[w], end = off[w + 1];
    float4 a0 = make_float4(0.f, 0.f, 0.f, 0.f);
    float4 a1 = make_float4(0.f, 0.f, 0.f, 0.f);
    int j = beg;
    for (; j + 3 < end; j += 4) {
        int m0 = mem[j], m1 = mem[j + 1], m2 = mem[j + 2], m3 = mem[j + 3];
        float4 v0 = *(const float4*)&src[(size_t)m0 * F1 + lane * 4];
        float4 v1 = *(const float4*)&src[(size_t)m1 * F1 + lane * 4];
        float4 v2 = *(const float4*)&src[(size_t)m2 * F1 + lane * 4];
        float4 v3 = *(const float4*)&src[(size_t)m3 * F1 + lane * 4];
        a0.x += v0.x; a0.y += v0.y; a0.z += v0.z; a0.w += v0.w;
        a1.x += v1.x; a1.y += v1.y; a1.z += v1.z; a1.w += v1.w;
        a0.x += v2.x; a0.y += v2.y; a0.z += v2.z; a0.w += v2.w;
        a1.x += v3.x; a1.y += v3.y; a1.z += v3.z; a1.w += v3.w;
    }
    for (; j < end; j++) {
        float4 v0 = *(const float4*)&src[(size_t)mem[j] * F1 + lane * 4];
        a0.x += v0.x; a0.y += v0.y; a0.z += v0.z; a0.w += v0.w;
    }
    float s = inv[w];
    float4 b = *(const float4*)&bias[lane * 4];
    float4 r = make_float4(fmaxf((a0.x + a1.x) * s + b.x, 0.f),
                           fmaxf((a0.y + a1.y) * s + b.y, 0.f),
                           fmaxf((a0.z + a1.z) * s + b.z, 0.f),
                           fmaxf((a0.w + a1.w) * s + b.w, 0.f));
    *(float4*)&hs[wl][lane * 4] = r;
    __syncwarp();

    // hw[c] = sum_k h[k] * W2[k][c]; half-warp splits k range, shfl combines
    const int c = lane & 15, kh = (lane >> 4) * 64;
    float acc = 0.f;
#pragma unroll 8
    for (int k = 0; k < 64; k++) acc += hs[wl][kh + k] * W2s[kh + k][c];
    acc += __shfl_down_sync(0xffffffffu, acc, 16);
    if (lane < 16) hw[(size_t)w * F2 + c] = acc;
}

// ---------------- gather-reduce F=16 ----------------
__global__ void gather16(const float* __restrict__ src, float* __restrict__ dst,
                         const int* __restrict__ mem, const int* __restrict__ off,
                         const float* __restrict__ inv, const float* __restrict__ bias,
                         int nrows) {
    int w = (blockIdx.x * blockDim.x + threadIdx.x) >> 5;
    int lane = threadIdx.x & 31;
    if (w >= nrows) return;
    int beg = off[w], end = off[w + 1];
    int half = lane >> 4, f = lane & 15;
    float acc = 0.f;
    for (int j = beg + half; j < end; j += 2)
        acc += src[(size_t)mem[j] * F2 + f];
    acc += __shfl_down_sync(0xffffffffu, acc, 16);
    if (lane < 16) {
        float r = acc * inv[w];
        if (bias) r += bias[f];
        dst[(size_t)w * F2 + f] = r;
    }
}

// ---------------- launcher ----------------
extern "C" void kernel_launch(void* const* d_in, const int* in_sizes, int n_in,
                              void* d_out, int out_size) {
    const float* x  = (const float*)d_in[0];
    const void*  ni = d_in[1];
    const void*  ei = d_in[2];
    const float* W1 = (const float*)d_in[n_in - 4];
    const float* b1 = (const float*)d_in[n_in - 3];
    const float* W2 = (const float*)d_in[n_in - 2];
    const float* b2 = (const float*)d_in[n_in - 1];
    const int nnz = in_sizes[1];
    const int M   = in_sizes[0] / F1;
    float* out = (float*)d_out;

    static bool  s_init = false;
    static cudaStream_t s2;
    static cudaEvent_t ev0, ev1;
    static int*   p_eoff, *p_noff, *p_emem, *p_nmem;
    static float* p_binv, *p_dinv, *p_xw, *p_ef, *p_hw, *p_ef2;
    if (!s_init) {
        cudaGetSymbolAddress((void**)&p_eoff, g_eoff);
        cudaGetSymbolAddress((void**)&p_noff, g_noff);
        cudaGetSymbolAddress((void**)&p_emem, g_e_members);
        cudaGetSymbolAddress((void**)&p_nmem, g_n_members);
        cudaGetSymbolAddress((void**)&p_binv, g_binv);
        cudaGetSymbolAddress((void**)&p_dinv, g_dinv);
        cudaGetSymbolAddress((void**)&p_xw,   g_xw);
        cudaGetSymbolAddress((void**)&p_ef,   g_efeat);
        cudaGetSymbolAddress((void**)&p_hw,   g_hw);
        cudaGetSymbolAddress((void**)&p_ef2,  g_efeat2);
        cudaStreamCreateWithFlags(&s2, cudaStreamNonBlocking);
        cudaEventCreateWithFlags(&ev0, cudaEventDisableTiming);
        cudaEventCreateWithFlags(&ev1, cudaEventDisableTiming);
        s_init = true;
    }

    // fork: GEMM1 on s2 overlaps the CSR build (CSR is latency-bound, SMs idle)
    cudaEventRecord(ev0, 0);
    cudaStreamWaitEvent(s2, ev0, 0);
    gemm1_tf32<<<(M + 127) / 128, 512, 0, s2>>>(x, W1, M);           // launch 1
    cudaEventRecord(ev1, s2);

    zero_detect_kernel<<<(N_NODES_C + 255) / 256, 256>>>(ni, nnz);   // launch 2
    hist_kernel<<<(nnz + 255) / 256, 256>>>(ni, ei, nnz);            // launch 3
    scan_fused_kernel<<<2, 1024>>>();                                // launch 4
    fill_kernel<<<(nnz + 255) / 256, 256>>>(ni, ei, nnz);            // launch 5

    cudaStreamWaitEvent(0, ev1, 0);  // join: gathers need GEMM1 output

    // layer 1: node->edge (Binv), then edge->node (Dinv, +b1, relu) fused with @W2
    int blocks_e = (N_EDGES_C * 32 + 255) / 256;
    int blocks_n = (N_NODES_C * 32 + 255) / 256;
    gather128<<<blocks_e, 256>>>(p_xw, p_ef, p_emem, p_eoff, p_binv, N_EDGES_C);  // launch 6 (ncu target)
    gather128_w2<<<blocks_n, 256>>>(p_ef, p_nmem, p_noff, p_dinv, b1, W2, p_hw, N_NODES_C);

    // layer 2
    gather16<<<blocks_e, 256>>>(p_hw,  p_ef2, p_emem, p_eoff, p_binv, nullptr, N_EDGES_C);
    gather16<<<blocks_n, 256>>>(p_ef2, out,   p_nmem, p_noff, p_dinv, b2,      N_NODES_C);
}

// round 5
// speedup vs baseline: 1.7519x; 1.7519x over previous
#include <cuda_runtime.h>
#include <cuda_fp16.h>

#define N_NODES_C 100000
#define N_EDGES_C 50000
#define NNZ_CAP   1600000
#define F1 128
#define F2 16
#define NB_E ((N_EDGES_C + 511) / 512)   // 98
#define NB_N ((N_NODES_C + 511) / 512)   // 196

// ---------------- static scratch (no cudaMalloc anywhere) ----------------
__device__ int   g_idx64;
__device__ int   g_ncnt[N_NODES_C];
__device__ int   g_ecnt[N_EDGES_C];
__device__ int   g_noff[N_NODES_C + 1];
__device__ int   g_eoff[N_EDGES_C + 1];
__device__ int   g_ncur[N_NODES_C];
__device__ int   g_ecur[N_EDGES_C];
__device__ int   g_bse[NB_E];
__device__ int   g_bsn[NB_N];
__device__ float g_dinv[N_NODES_C];
__device__ float g_binv[N_EDGES_C];
__device__ int   g_e_members[NNZ_CAP];         // node ids grouped by edge
__device__ int   g_n_members[NNZ_CAP];         // edge ids grouped by node
__device__ __align__(16) __half g_xw[(size_t)N_NODES_C * F1];     // x@W1, fp16
__device__ __align__(16) __half g_efeat[(size_t)N_EDGES_C * F1];  // edge feats, fp16
__device__ __align__(16) float  g_hw[(size_t)N_NODES_C * F2];
__device__ __align__(16) float  g_efeat2[(size_t)N_EDGES_C * F2];

__device__ __forceinline__ int load_idx(const void* p, int i, int is64) {
    return is64 ? (int)((const long long*)p)[i] : ((const int*)p)[i];
}

// ---------------- zero counters + detect index dtype (fused) ----------------
__global__ void zero_detect_kernel(const void* ni, int nnz) {
    __shared__ int bad_s;
    int i = blockIdx.x * blockDim.x + threadIdx.x;
    if (i < N_NODES_C) g_ncnt[i] = 0;
    if (i < N_EDGES_C) g_ecnt[i] = 0;
    if (blockIdx.x == 0) {
        if (threadIdx.x == 0) bad_s = 0;
        __syncthreads();
        int k = nnz < 64 ? nnz : 64;
        if ((int)threadIdx.x < k) {
            long long v = ((const long long*)ni)[threadIdx.x];
            if (v < 0 || v >= (1LL << 31)) atomicOr(&bad_s, 1);
        }
        __syncthreads();
        if (threadIdx.x == 0) g_idx64 = bad_s ? 0 : 1;
    }
}

// ---------------- histogram ----------------
__global__ void hist_kernel(const void* ni, const void* ei, int nnz) {
    int i = blockIdx.x * blockDim.x + threadIdx.x;
    if (i >= nnz) return;
    int is64 = g_idx64;
    atomicAdd(&g_ncnt[load_idx(ni, i, is64)], 1);
    atomicAdd(&g_ecnt[load_idx(ei, i, is64)], 1);
}

// ---------------- coalesced 3-phase scan, edges+nodes in one grid ----------------
__global__ __launch_bounds__(512) void bsums_kernel() {
    __shared__ int s[512];
    const bool edges = blockIdx.x < NB_E;
    const int  b   = edges ? blockIdx.x : blockIdx.x - NB_E;
    const int* cnt = edges ? g_ecnt : g_ncnt;
    const int  n   = edges ? N_EDGES_C : N_NODES_C;
    int i = b * 512 + threadIdx.x;
    s[threadIdx.x] = (i < n) ? cnt[i] : 0;
    __syncthreads();
    for (int d = 256; d > 0; d >>= 1) {
        if ((int)threadIdx.x < d) s[threadIdx.x] += s[threadIdx.x + d];
        __syncthreads();
    }
    if (threadIdx.x == 0) (edges ? g_bse : g_bsn)[b] = s[0];
}

__global__ __launch_bounds__(512) void scanmid_kernel() {
    __shared__ int s[512];
    const int tid = threadIdx.x;
    // pass 0: edges block sums (98), pass 1: nodes block sums (196)
    for (int pass = 0; pass < 2; pass++) {
        int* b = pass ? g_bsn : g_bse;
        int nb = pass ? NB_N : NB_E;
        int v = (tid < nb) ? b[tid] : 0;
        s[tid] = v;
        __syncthreads();
        for (int d = 1; d < 512; d <<= 1) {
            int t = (tid >= d) ? s[tid - d] : 0;
            __syncthreads();
            s[tid] += t;
            __syncthreads();
        }
        if (tid < nb) b[tid] = s[tid] - v;   // exclusive
        __syncthreads();
    }
}

__global__ __launch_bounds__(512) void apply_kernel() {
    __shared__ int s[512];
    const int tid = threadIdx.x;
    const bool edges = blockIdx.x < NB_E;
    const int  b   = edges ? blockIdx.x : blockIdx.x - NB_E;
    const int* cnt = edges ? g_ecnt : g_ncnt;
    int*   off = edges ? g_eoff : g_noff;
    int*   cur = edges ? g_ecur : g_ncur;
    float* inv = edges ? g_binv : g_dinv;
    const int n = edges ? N_EDGES_C : N_NODES_C;
    int i = b * 512 + tid;
    int v = (i < n) ? cnt[i] : 0;
    s[tid] = v;
    __syncthreads();
    for (int d = 1; d < 512; d <<= 1) {
        int t = (tid >= d) ? s[tid - d] : 0;
        __syncthreads();
        s[tid] += t;
        __syncthreads();
    }
    int base = (edges ? g_bse : g_bsn)[b];
    if (i < n) {
        int o = base + s[tid] - v;
        off[i] = o;
        cur[i] = o;
        inv[i] = v > 0 ? 1.f / (float)v : 0.f;
        if (i == n - 1) off[n] = base + s[tid];
    }
}

// ---------------- fill CSR member lists ----------------
__global__ void fill_kernel(const void* ni, const void* ei, int nnz) {
    int i = blockIdx.x * blockDim.x + threadIdx.x;
    if (i >= nnz) return;
    int is64 = g_idx64;
    int n = load_idx(ni, i, is64);
    int e = load_idx(ei, i, is64);
    g_e_members[atomicAdd(&g_ecur[e], 1)] = n;
    g_n_members[atomicAdd(&g_ncur[n], 1)] = e;
}

// ---------------- GEMM1: tensor-core tf32 (3-pass compensated), fp16 output ------
__device__ __forceinline__ void split_tf32(float x, unsigned& hi, unsigned& lo) {
    asm("cvt.rna.tf32.f32 %0, %1;" : "=r"(hi) : "f"(x));
    float r = x - __uint_as_float(hi);
    asm("cvt.rna.tf32.f32 %0, %1;" : "=r"(lo) : "f"(r));
}

__device__ __forceinline__ void mma_tf32(float* c, unsigned a0, unsigned a1,
                                         unsigned a2, unsigned a3,
                                         unsigned b0, unsigned b1) {
    asm("mma.sync.aligned.m16n8k8.row.col.f32.tf32.tf32.f32 "
        "{%0,%1,%2,%3}, {%4,%5,%6,%7}, {%8,%9}, {%0,%1,%2,%3};"
        : "+f"(c[0]), "+f"(c[1]), "+f"(c[2]), "+f"(c[3])
        : "r"(a0), "r"(a1), "r"(a2), "r"(a3), "r"(b0), "r"(b1));
}

__global__ __launch_bounds__(512) void gemm1_tf32(const float* __restrict__ A,
                                                  const float* __restrict__ W, int M) {
    __shared__ unsigned Ah[128][20], Al[128][20];
    __shared__ unsigned Bh[16][132], Bl[16][132];
    const int tid  = threadIdx.x;
    const int wid  = tid >> 5, lane = tid & 31;
    const int g = lane >> 2, t = lane & 3;
    const int wm = (wid >> 2) * 32;
    const int wn = (wid & 3) * 32;
    const int mbase = blockIdx.x * 128;

    float acc[2][4][4];
#pragma unroll
    for (int a = 0; a < 2; a++)
#pragma unroll
        for (int b = 0; b < 4; b++)
#pragma unroll
            for (int c = 0; c < 4; c++) acc[a][b][c] = 0.f;

    const int ar  = tid >> 2;
    const int ac4 = tid & 3;
    const int br  = tid >> 5;
    const int bc4 = tid & 31;
    const bool avalid = (mbase + ar) < M;
    const float* Arow = A + (size_t)(mbase + ar) * 128;

    for (int kc = 0; kc < 128; kc += 16) {
        float4 av = avalid ? *(const float4*)(Arow + kc + ac4 * 4)
                           : make_float4(0.f, 0.f, 0.f, 0.f);
        float4 bv = *(const float4*)(W + (size_t)(kc + br) * 128 + bc4 * 4);
        unsigned h, l;
        split_tf32(av.x, h, l); Ah[ar][ac4 * 4 + 0] = h; Al[ar][ac4 * 4 + 0] = l;
        split_tf32(av.y, h, l); Ah[ar][ac4 * 4 + 1] = h; Al[ar][ac4 * 4 + 1] = l;
        split_tf32(av.z, h, l); Ah[ar][ac4 * 4 + 2] = h; Al[ar][ac4 * 4 + 2] = l;
        split_tf32(av.w, h, l); Ah[ar][ac4 * 4 + 3] = h; Al[ar][ac4 * 4 + 3] = l;
        split_tf32(bv.x, h, l); Bh[br][bc4 * 4 + 0] = h; Bl[br][bc4 * 4 + 0] = l;
        split_tf32(bv.y, h, l); Bh[br][bc4 * 4 + 1] = h; Bl[br][bc4 * 4 + 1] = l;
        split_tf32(bv.z, h, l); Bh[br][bc4 * 4 + 2] = h; Bl[br][bc4 * 4 + 2] = l;
        split_tf32(bv.w, h, l); Bh[br][bc4 * 4 + 3] = h; Bl[br][bc4 * 4 + 3] = l;
        __syncthreads();

#pragma unroll
        for (int ks = 0; ks < 2; ks++) {
            const int k0 = ks * 8;
            unsigned bh[4][2], bl[4][2];
#pragma unroll
            for (int nt = 0; nt < 4; nt++) {
                int cn = wn + nt * 8 + g;
                bh[nt][0] = Bh[k0 + t][cn];
                bh[nt][1] = Bh[k0 + t + 4][cn];
                bl[nt][0] = Bl[k0 + t][cn];
                bl[nt][1] = Bl[k0 + t + 4][cn];
            }
#pragma unroll
            for (int mt = 0; mt < 2; mt++) {
                const int rm = wm + mt * 16;
                unsigned ah0 = Ah[rm + g][k0 + t];
                unsigned ah1 = Ah[rm + g + 8][k0 + t];
                unsigned ah2 = Ah[rm + g][k0 + t + 4];
                unsigned ah3 = Ah[rm + g + 8][k0 + t + 4];
                unsigned al0 = Al[rm + g][k0 + t];
                unsigned al1 = Al[rm + g + 8][k0 + t];
                unsigned al2 = Al[rm + g][k0 + t + 4];
                unsigned al3 = Al[rm + g + 8][k0 + t + 4];
#pragma unroll
                for (int nt = 0; nt < 4; nt++) {
                    mma_tf32(acc[mt][nt], ah0, ah1, ah2, ah3, bh[nt][0], bh[nt][1]);
                    mma_tf32(acc[mt][nt], ah0, ah1, ah2, ah3, bl[nt][0], bl[nt][1]);
                    mma_tf32(acc[mt][nt], al0, al1, al2, al3, bh[nt][0], bh[nt][1]);
                }
            }
        }
        __syncthreads();
    }

#pragma unroll
    for (int mt = 0; mt < 2; mt++) {
#pragma unroll
        for (int nt = 0; nt < 4; nt++) {
            int row = mbase + wm + mt * 16 + g;
            int col = wn + nt * 8 + 2 * t;
            if (row < M)
                *(__half2*)&g_xw[(size_t)row * 128 + col] =
                    __floats2half2_rn(acc[mt][nt][0], acc[mt][nt][1]);
            if (row + 8 < M)
                *(__half2*)&g_xw[(size_t)(row + 8) * 128 + col] =
                    __floats2half2_rn(acc[mt][nt][2], acc[mt][nt][3]);
        }
    }
}

// ---------------- gather-reduce F=128 fp16 (warp per row) ----------------
__device__ __forceinline__ void acc_h4(float4& a, uint2 raw) {
    __half2 h01 = *(__half2*)&raw.x;
    __half2 h23 = *(__half2*)&raw.y;
    float2 f01 = __half22float2(h01);
    float2 f23 = __half22float2(h23);
    a.x += f01.x; a.y += f01.y; a.z += f23.x; a.w += f23.y;
}

__global__ __launch_bounds__(256) void gather128h(const __half* __restrict__ src,
                                                  __half* __restrict__ dst,
                                                  const int* __restrict__ mem,
                                                  const int* __restrict__ off,
                                                  const float* __restrict__ inv,
                                                  int nrows) {
    int w = (blockIdx.x * blockDim.x + threadIdx.x) >> 5;
    int lane = threadIdx.x & 31;
    if (w >= nrows) return;
    int beg = off[w], end = off[w + 1];
    float4 a = make_float4(0.f, 0.f, 0.f, 0.f);
    int j = beg;
    for (; j + 3 < end; j += 4) {
        int m0 = mem[j], m1 = mem[j + 1], m2 = mem[j + 2], m3 = mem[j + 3];
        uint2 r0 = *(const uint2*)&src[(size_t)m0 * F1 + lane * 4];
        uint2 r1 = *(const uint2*)&src[(size_t)m1 * F1 + lane * 4];
        uint2 r2 = *(const uint2*)&src[(size_t)m2 * F1 + lane * 4];
        uint2 r3 = *(const uint2*)&src[(size_t)m3 * F1 + lane * 4];
        acc_h4(a, r0); acc_h4(a, r1); acc_h4(a, r2); acc_h4(a, r3);
    }
    for (; j < end; j++) {
        uint2 r0 = *(const uint2*)&src[(size_t)mem[j] * F1 + lane * 4];
        acc_h4(a, r0);
    }
    float s = inv[w];
    uint2 o;
    *(__half2*)&o.x = __floats2half2_rn(a.x * s, a.y * s);
    *(__half2*)&o.y = __floats2half2_rn(a.z * s, a.w * s);
    *(uint2*)&dst[(size_t)w * F1 + lane * 4] = o;
}

// ------- gather-reduce F=128 fp16 + bias + relu + fused [128x16] W2 multiply -------
__global__ __launch_bounds__(256) void gather128h_w2(const __half* __restrict__ src,
                                                     const int* __restrict__ mem,
                                                     const int* __restrict__ off,
                                                     const float* __restrict__ inv,
                                                     const float* __restrict__ bias,
                                                     const float* __restrict__ W2,
                                                     float* __restrict__ hw, int nrows) {
    __shared__ float W2s[128][17];
    __shared__ float hs[8][128];
    const int tid = threadIdx.x;
    for (int i = tid; i < 128 * 16; i += 256) W2s[i >> 4][i & 15] = W2[i];
    __syncthreads();

    int w = (blockIdx.x * blockDim.x + tid) >> 5;
    int lane = tid & 31, wl = tid >> 5;
    if (w >= nrows) return;
    int beg = off[w], end = off[w + 1];
    float4 a = make_float4(0.f, 0.f, 0.f, 0.f);
    int j = beg;
    for (; j + 3 < end; j += 4) {
        int m0 = mem[j], m1 = mem[j + 1], m2 = mem[j + 2], m3 = mem[j + 3];
        uint2 r0 = *(const uint2*)&src[(size_t)m0 * F1 + lane * 4];
        uint2 r1 = *(const uint2*)&src[(size_t)m1 * F1 + lane * 4];
        uint2 r2 = *(const uint2*)&src[(size_t)m2 * F1 + lane * 4];
        uint2 r3 = *(const uint2*)&src[(size_t)m3 * F1 + lane * 4];
        acc_h4(a, r0); acc_h4(a, r1); acc_h4(a, r2); acc_h4(a, r3);
    }
    for (; j < end; j++) {
        uint2 r0 = *(const uint2*)&src[(size_t)mem[j] * F1 + lane * 4];
        acc_h4(a, r0);
    }
    float s = inv[w];
    float4 b = *(const float4*)&bias[lane * 4];
    hs[wl][lane * 4 + 0] = fmaxf(a.x * s + b.x, 0.f);
    hs[wl][lane * 4 + 1] = fmaxf(a.y * s + b.y, 0.f);
    hs[wl][lane * 4 + 2] = fmaxf(a.z * s + b.z, 0.f);
    hs[wl][lane * 4 + 3] = fmaxf(a.w * s + b.w, 0.f);
    __syncwarp();

    // hw[c] = sum_k h[k] * W2[k][c]; half-warp splits k, shfl combines
    const int c = lane & 15, kh = (lane >> 4) * 64;
    float acc = 0.f;
#pragma unroll 8
    for (int k = 0; k < 64; k++) acc += hs[wl][kh + k] * W2s[kh + k][c];
    acc += __shfl_down_sync(0xffffffffu, acc, 16);
    if (lane < 16) hw[(size_t)w * F2 + c] = acc;
}

// ---------------- gather-reduce F=16 (fp32) ----------------
__global__ void gather16(const float* __restrict__ src, float* __restrict__ dst,
                         const int* __restrict__ mem, const int* __restrict__ off,
                         const float* __restrict__ inv, const float* __restrict__ bias,
                         int nrows) {
    int w = (blockIdx.x * blockDim.x + threadIdx.x) >> 5;
    int lane = threadIdx.x & 31;
    if (w >= nrows) return;
    int beg = off[w], end = off[w + 1];
    int half = lane >> 4, f = lane & 15;
    float acc = 0.f;
    for (int j = beg + half; j < end; j += 2)
        acc += src[(size_t)mem[j] * F2 + f];
    acc += __shfl_down_sync(0xffffffffu, acc, 16);
    if (lane < 16) {
        float r = acc * inv[w];
        if (bias) r += bias[f];
        dst[(size_t)w * F2 + f] = r;
    }
}

// ---------------- launcher ----------------
extern "C" void kernel_launch(void* const* d_in, const int* in_sizes, int n_in,
                              void* d_out, int out_size) {
    const float* x  = (const float*)d_in[0];
    const void*  ni = d_in[1];
    const void*  ei = d_in[2];
    const float* W1 = (const float*)d_in[n_in - 4];
    const float* b1 = (const float*)d_in[n_in - 3];
    const float* W2 = (const float*)d_in[n_in - 2];
    const float* b2 = (const float*)d_in[n_in - 1];
    const int nnz = in_sizes[1];
    const int M   = in_sizes[0] / F1;
    float* out = (float*)d_out;

    static bool  s_init = false;
    static cudaStream_t s2;
    static cudaEvent_t ev0, ev1;
    static int*    p_eoff, *p_noff, *p_emem, *p_nmem;
    static float*  p_binv, *p_dinv, *p_hw, *p_ef2;
    static __half* p_xw, *p_ef;
    if (!s_init) {
        cudaGetSymbolAddress((void**)&p_eoff, g_eoff);
        cudaGetSymbolAddress((void**)&p_noff, g_noff);
        cudaGetSymbolAddress((void**)&p_emem, g_e_members);
        cudaGetSymbolAddress((void**)&p_nmem, g_n_members);
        cudaGetSymbolAddress((void**)&p_binv, g_binv);
        cudaGetSymbolAddress((void**)&p_dinv, g_dinv);
        cudaGetSymbolAddress((void**)&p_xw,   g_xw);
        cudaGetSymbolAddress((void**)&p_ef,   g_efeat);
        cudaGetSymbolAddress((void**)&p_hw,   g_hw);
        cudaGetSymbolAddress((void**)&p_ef2,  g_efeat2);
        cudaStreamCreateWithFlags(&s2, cudaStreamNonBlocking);
        cudaEventCreateWithFlags(&ev0, cudaEventDisableTiming);
        cudaEventCreateWithFlags(&ev1, cudaEventDisableTiming);
        s_init = true;
    }

    // fork: GEMM1 on s2 overlaps the CSR build (CSR is latency-bound, SMs idle)
    cudaEventRecord(ev0, 0);
    cudaStreamWaitEvent(s2, ev0, 0);
    gemm1_tf32<<<(M + 127) / 128, 512, 0, s2>>>(x, W1, M);
    cudaEventRecord(ev1, s2);

    // CSR build on default stream (coalesced, wide kernels)
    zero_detect_kernel<<<(N_NODES_C + 255) / 256, 256>>>(ni, nnz);
    hist_kernel<<<(nnz + 255) / 256, 256>>>(ni, ei, nnz);
    bsums_kernel<<<NB_E + NB_N, 512>>>();
    scanmid_kernel<<<1, 512>>>();
    apply_kernel<<<NB_E + NB_N, 512>>>();
    fill_kernel<<<(nnz + 255) / 256, 256>>>(ni, ei, nnz);

    cudaStreamWaitEvent(0, ev1, 0);  // join: gathers need GEMM1 output

    // layer 1: node->edge (Binv), then edge->node (Dinv, +b1, relu) fused with @W2
    int blocks_e = (N_EDGES_C * 32 + 255) / 256;
    int blocks_n = (N_NODES_C * 32 + 255) / 256;
    gather128h<<<blocks_e, 256>>>(p_xw, p_ef, p_emem, p_eoff, p_binv, N_EDGES_C);
    gather128h_w2<<<blocks_n, 256>>>(p_ef, p_nmem, p_noff, p_dinv, b1, W2, p_hw, N_NODES_C);

    // layer 2
    gather16<<<blocks_e, 256>>>(p_hw,  p_ef2, p_emem, p_eoff, p_binv, nullptr, N_EDGES_C);
    gather16<<<blocks_n, 256>>>(p_ef2, out,   p_nmem, p_noff, p_dinv, b2,      N_NODES_C);
}

// round 6
// speedup vs baseline: 1.9531x; 1.1149x over previous
#include <cuda_runtime.h>
#include <cuda_fp16.h>

#define N_NODES_C 100000
#define N_EDGES_C 50000
#define NNZ_CAP   1600000
#define F1 128
#define F2 16
#define NB_E ((N_EDGES_C + 511) / 512)   // 98
#define NB_N ((N_NODES_C + 511) / 512)   // 196

// ---------------- static scratch (no cudaMalloc anywhere) ----------------
__device__ int   g_idx64;
__device__ int   g_ncnt[N_NODES_C];
__device__ int   g_ecnt[N_EDGES_C];
__device__ int   g_noff[N_NODES_C + 1];
__device__ int   g_eoff[N_EDGES_C + 1];
__device__ int   g_ncur[N_NODES_C];
__device__ int   g_ecur[N_EDGES_C];
__device__ int   g_bse[NB_E];
__device__ int   g_bsn[NB_N];
__device__ float g_dinv[N_NODES_C];
__device__ float g_binv[N_EDGES_C];
__device__ int   g_e_members[NNZ_CAP];                            // node ids grouped by edge
__device__ int   g_n_members[NNZ_CAP];                            // edge ids grouped by node
__device__ __align__(16) __half g_xh[(size_t)N_NODES_C * F1];     // x in fp16
__device__ __align__(16) __half g_agg[(size_t)N_EDGES_C * F1];    // Binv * segsum(x) per edge
__device__ __align__(16) __half g_ef[(size_t)N_EDGES_C * F1];     // agg @ W1
__device__ __align__(16) float  g_hw[(size_t)N_NODES_C * F2];
__device__ __align__(16) float  g_efeat2[(size_t)N_EDGES_C * F2];

__device__ __forceinline__ int load_idx(const void* p, int i, int is64) {
    return is64 ? (int)((const long long*)p)[i] : ((const int*)p)[i];
}

// ---------------- x -> fp16 (runs on s2, hidden under CSR build) ----------------
__global__ void convert_half_kernel(const float* __restrict__ x,
                                    __half* __restrict__ xh, int n4) {
    int i = blockIdx.x * blockDim.x + threadIdx.x;
    if (i < n4) {
        float4 v = ((const float4*)x)[i];
        uint2 o;
        *(__half2*)&o.x = __floats2half2_rn(v.x, v.y);
        *(__half2*)&o.y = __floats2half2_rn(v.z, v.w);
        ((uint2*)xh)[i] = o;
    }
}

// ---------------- zero counters + detect index dtype (fused) ----------------
__global__ void zero_detect_kernel(const void* ni, int nnz) {
    __shared__ int bad_s;
    int i = blockIdx.x * blockDim.x + threadIdx.x;
    if (i < N_NODES_C) g_ncnt[i] = 0;
    if (i < N_EDGES_C) g_ecnt[i] = 0;
    if (blockIdx.x == 0) {
        if (threadIdx.x == 0) bad_s = 0;
        __syncthreads();
        int k = nnz < 64 ? nnz : 64;
        if ((int)threadIdx.x < k) {
            long long v = ((const long long*)ni)[threadIdx.x];
            if (v < 0 || v >= (1LL << 31)) atomicOr(&bad_s, 1);
        }
        __syncthreads();
        if (threadIdx.x == 0) g_idx64 = bad_s ? 0 : 1;
    }
}

// ---------------- histogram ----------------
__global__ void hist_kernel(const void* ni, const void* ei, int nnz) {
    int i = blockIdx.x * blockDim.x + threadIdx.x;
    if (i >= nnz) return;
    int is64 = g_idx64;
    atomicAdd(&g_ncnt[load_idx(ni, i, is64)], 1);
    atomicAdd(&g_ecnt[load_idx(ei, i, is64)], 1);
}

// ---------------- coalesced 3-phase scan, edges+nodes in one grid ----------------
__global__ __launch_bounds__(512) void bsums_kernel() {
    __shared__ int s[512];
    const bool edges = blockIdx.x < NB_E;
    const int  b   = edges ? blockIdx.x : blockIdx.x - NB_E;
    const int* cnt = edges ? g_ecnt : g_ncnt;
    const int  n   = edges ? N_EDGES_C : N_NODES_C;
    int i = b * 512 + threadIdx.x;
    s[threadIdx.x] = (i < n) ? cnt[i] : 0;
    __syncthreads();
    for (int d = 256; d > 0; d >>= 1) {
        if ((int)threadIdx.x < d) s[threadIdx.x] += s[threadIdx.x + d];
        __syncthreads();
    }
    if (threadIdx.x == 0) (edges ? g_bse : g_bsn)[b] = s[0];
}

__global__ __launch_bounds__(512) void scanmid_kernel() {
    __shared__ int s[512];
    const int tid = threadIdx.x;
    for (int pass = 0; pass < 2; pass++) {
        int* b = pass ? g_bsn : g_bse;
        int nb = pass ? NB_N : NB_E;
        int v = (tid < nb) ? b[tid] : 0;
        s[tid] = v;
        __syncthreads();
        for (int d = 1; d < 512; d <<= 1) {
            int t = (tid >= d) ? s[tid - d] : 0;
            __syncthreads();
            s[tid] += t;
            __syncthreads();
        }
        if (tid < nb) b[tid] = s[tid] - v;
        __syncthreads();
    }
}

__global__ __launch_bounds__(512) void apply_kernel() {
    __shared__ int s[512];
    const int tid = threadIdx.x;
    const bool edges = blockIdx.x < NB_E;
    const int  b   = edges ? blockIdx.x : blockIdx.x - NB_E;
    const int* cnt = edges ? g_ecnt : g_ncnt;
    int*   off = edges ? g_eoff : g_noff;
    int*   cur = edges ? g_ecur : g_ncur;
    float* inv = edges ? g_binv : g_dinv;
    const int n = edges ? N_EDGES_C : N_NODES_C;
    int i = b * 512 + tid;
    int v = (i < n) ? cnt[i] : 0;
    s[tid] = v;
    __syncthreads();
    for (int d = 1; d < 512; d <<= 1) {
        int t = (tid >= d) ? s[tid - d] : 0;
        __syncthreads();
        s[tid] += t;
        __syncthreads();
    }
    int base = (edges ? g_bse : g_bsn)[b];
    if (i < n) {
        int o = base + s[tid] - v;
        off[i] = o;
        cur[i] = o;
        inv[i] = v > 0 ? 1.f / (float)v : 0.f;
        if (i == n - 1) off[n] = base + s[tid];
    }
}

// ---------------- fill CSR member lists (split: edge list / node list) --------------
__global__ void fill_e_kernel(const void* ni, const void* ei, int nnz) {
    int i = blockIdx.x * blockDim.x + threadIdx.x;
    if (i >= nnz) return;
    int is64 = g_idx64;
    int n = load_idx(ni, i, is64);
    int e = load_idx(ei, i, is64);
    g_e_members[atomicAdd(&g_ecur[e], 1)] = n;
}

__global__ void fill_n_kernel(const void* ni, const void* ei, int nnz) {
    int i = blockIdx.x * blockDim.x + threadIdx.x;
    if (i >= nnz) return;
    int is64 = g_idx64;
    int n = load_idx(ni, i, is64);
    int e = load_idx(ei, i, is64);
    g_n_members[atomicAdd(&g_ncur[n], 1)] = e;
}

// ---------------- edge-level GEMM: [M,128] fp16 @ [128,128] fp32 -> fp16 ----------
// 2-pass fp16: W1 split into fp16 hi+lo (A is exactly fp16 -> no A error).
__device__ __forceinline__ void mma_f16(float* c, unsigned a0, unsigned a1,
                                        unsigned a2, unsigned a3,
                                        unsigned b0, unsigned b1) {
    asm("mma.sync.aligned.m16n8k16.row.col.f32.f16.f16.f32 "
        "{%0,%1,%2,%3}, {%4,%5,%6,%7}, {%8,%9}, {%0,%1,%2,%3};"
        : "+f"(c[0]), "+f"(c[1]), "+f"(c[2]), "+f"(c[3])
        : "r"(a0), "r"(a1), "r"(a2), "r"(a3), "r"(b0), "r"(b1));
}

__global__ __launch_bounds__(512) void gemm_e_f16(const __half* __restrict__ A,
                                                  const float* __restrict__ W,
                                                  __half* __restrict__ out, int M) {
    __shared__ __half As[128][40];          // [m][k-chunk], pad 40
    __shared__ __half Bh[128][40];          // [n][k-chunk] (transposed), hi
    __shared__ __half Bl[128][40];          // lo
    const int tid = threadIdx.x;
    const int wid = tid >> 5, lane = tid & 31;
    const int g = lane >> 2, t = lane & 3;
    const int wm = (wid >> 2) * 32, wn = (wid & 3) * 32;
    const int mbase = blockIdx.x * 128;

    float acc[2][4][4];
#pragma unroll
    for (int a = 0; a < 2; a++)
#pragma unroll
        for (int b = 0; b < 4; b++)
#pragma unroll
            for (int c = 0; c < 4; c++) acc[a][b][c] = 0.f;

    for (int kc = 0; kc < 128; kc += 32) {
        // A chunk: 128 rows x 32 halves (uint2 = 4 halves per load)
#pragma unroll
        for (int i = 0; i < 2; i++) {
            int idx = tid + i * 512;             // 0..1023
            int r = idx >> 3, q = idx & 7;
            int row = mbase + r;
            uint2 v = (row < M) ? *(const uint2*)&A[(size_t)row * 128 + kc + q * 4]
                                : make_uint2(0u, 0u);
            *(uint2*)&As[r][q * 4] = v;
        }
        // W chunk: 32 k-rows x 128 n; split into hi/lo, store transposed [n][k]
#pragma unroll
        for (int i = 0; i < 2; i++) {
            int idx = tid + i * 512;             // 0..1023
            int kr = idx >> 5, nc4 = idx & 31;
            float4 w4 = *(const float4*)&W[(size_t)(kc + kr) * 128 + nc4 * 4];
            float wv[4] = {w4.x, w4.y, w4.z, w4.w};
#pragma unroll
            for (int j = 0; j < 4; j++) {
                __half hi = __float2half_rn(wv[j]);
                __half lo = __float2half_rn(wv[j] - __half2float(hi));
                Bh[nc4 * 4 + j][kr] = hi;
                Bl[nc4 * 4 + j][kr] = lo;
            }
        }
        __syncthreads();

#pragma unroll
        for (int ks = 0; ks < 2; ks++) {
            const int k0 = ks * 16;
#pragma unroll
            for (int mt = 0; mt < 2; mt++) {
                const int rm = wm + mt * 16;
                unsigned a0 = *(unsigned*)&As[rm + g][k0 + 2 * t];
                unsigned a1 = *(unsigned*)&As[rm + g + 8][k0 + 2 * t];
                unsigned a2 = *(unsigned*)&As[rm + g][k0 + 2 * t + 8];
                unsigned a3 = *(unsigned*)&As[rm + g + 8][k0 + 2 * t + 8];
#pragma unroll
                for (int nt = 0; nt < 4; nt++) {
                    int n = wn + nt * 8 + g;
                    unsigned bh0 = *(unsigned*)&Bh[n][k0 + 2 * t];
                    unsigned bh1 = *(unsigned*)&Bh[n][k0 + 2 * t + 8];
                    unsigned bl0 = *(unsigned*)&Bl[n][k0 + 2 * t];
                    unsigned bl1 = *(unsigned*)&Bl[n][k0 + 2 * t + 8];
                    mma_f16(acc[mt][nt], a0, a1, a2, a3, bh0, bh1);
                    mma_f16(acc[mt][nt], a0, a1, a2, a3, bl0, bl1);
                }
            }
        }
        __syncthreads();
    }

#pragma unroll
    for (int mt = 0; mt < 2; mt++) {
#pragma unroll
        for (int nt = 0; nt < 4; nt++) {
            int row = mbase + wm + mt * 16 + g;
            int col = wn + nt * 8 + 2 * t;
            if (row < M)
                *(__half2*)&out[(size_t)row * 128 + col] =
                    __floats2half2_rn(acc[mt][nt][0], acc[mt][nt][1]);
            if (row + 8 < M)
                *(__half2*)&out[(size_t)(row + 8) * 128 + col] =
                    __floats2half2_rn(acc[mt][nt][2], acc[mt][nt][3]);
        }
    }
}

// ---------------- gather-reduce F=128 fp16 (warp per row) ----------------
__device__ __forceinline__ void acc_h4(float4& a, uint2 raw) {
    float2 f01 = __half22float2(*(__half2*)&raw.x);
    float2 f23 = __half22float2(*(__half2*)&raw.y);
    a.x += f01.x; a.y += f01.y; a.z += f23.x; a.w += f23.y;
}

__global__ __launch_bounds__(256) void gather128h(const __half* __restrict__ src,
                                                  __half* __restrict__ dst,
                                                  const int* __restrict__ mem,
                                                  const int* __restrict__ off,
                                                  const float* __restrict__ inv,
                                                  int nrows) {
    int w = (blockIdx.x * blockDim.x + threadIdx.x) >> 5;
    int lane = threadIdx.x & 31;
    if (w >= nrows) return;
    int beg = off[w], end = off[w + 1];
    float4 a = make_float4(0.f, 0.f, 0.f, 0.f);
    int j = beg;
    for (; j + 3 < end; j += 4) {
        int m0 = mem[j], m1 = mem[j + 1], m2 = mem[j + 2], m3 = mem[j + 3];
        uint2 r0 = *(const uint2*)&src[(size_t)m0 * F1 + lane * 4];
        uint2 r1 = *(const uint2*)&src[(size_t)m1 * F1 + lane * 4];
        uint2 r2 = *(const uint2*)&src[(size_t)m2 * F1 + lane * 4];
        uint2 r3 = *(const uint2*)&src[(size_t)m3 * F1 + lane * 4];
        acc_h4(a, r0); acc_h4(a, r1); acc_h4(a, r2); acc_h4(a, r3);
    }
    for (; j < end; j++) {
        uint2 r0 = *(const uint2*)&src[(size_t)mem[j] * F1 + lane * 4];
        acc_h4(a, r0);
    }
    float s = inv[w];
    uint2 o;
    *(__half2*)&o.x = __floats2half2_rn(a.x * s, a.y * s);
    *(__half2*)&o.y = __floats2half2_rn(a.z * s, a.w * s);
    *(uint2*)&dst[(size_t)w * F1 + lane * 4] = o;
}

// ------- gather-reduce F=128 fp16 + bias + relu + fused [128x16] W2 multiply -------
__global__ __launch_bounds__(256) void gather128h_w2(const __half* __restrict__ src,
                                                     const int* __restrict__ mem,
                                                     const int* __restrict__ off,
                                                     const float* __restrict__ inv,
                                                     const float* __restrict__ bias,
                                                     const float* __restrict__ W2,
                                                     float* __restrict__ hw, int nrows) {
    __shared__ float W2s[128][17];
    __shared__ float hs[8][128];
    const int tid = threadIdx.x;
    for (int i = tid; i < 128 * 16; i += 256) W2s[i >> 4][i & 15] = W2[i];
    __syncthreads();

    int w = (blockIdx.x * blockDim.x + tid) >> 5;
    int lane = tid & 31, wl = tid >> 5;
    if (w >= nrows) return;
    int beg = off[w], end = off[w + 1];
    float4 a = make_float4(0.f, 0.f, 0.f, 0.f);
    int j = beg;
    for (; j + 3 < end; j += 4) {
        int m0 = mem[j], m1 = mem[j + 1], m2 = mem[j + 2], m3 = mem[j + 3];
        uint2 r0 = *(const uint2*)&src[(size_t)m0 * F1 + lane * 4];
        uint2 r1 = *(const uint2*)&src[(size_t)m1 * F1 + lane * 4];
        uint2 r2 = *(const uint2*)&src[(size_t)m2 * F1 + lane * 4];
        uint2 r3 = *(const uint2*)&src[(size_t)m3 * F1 + lane * 4];
        acc_h4(a, r0); acc_h4(a, r1); acc_h4(a, r2); acc_h4(a, r3);
    }
    for (; j < end; j++) {
        uint2 r0 = *(const uint2*)&src[(size_t)mem[j] * F1 + lane * 4];
        acc_h4(a, r0);
    }
    float s = inv[w];
    float4 b = *(const float4*)&bias[lane * 4];
    hs[wl][lane * 4 + 0] = fmaxf(a.x * s + b.x, 0.f);
    hs[wl][lane * 4 + 1] = fmaxf(a.y * s + b.y, 0.f);
    hs[wl][lane * 4 + 2] = fmaxf(a.z * s + b.z, 0.f);
    hs[wl][lane * 4 + 3] = fmaxf(a.w * s + b.w, 0.f);
    __syncwarp();

    const int c = lane & 15, kh = (lane >> 4) * 64;
    float acc = 0.f;
#pragma unroll 8
    for (int k = 0; k < 64; k++) acc += hs[wl][kh + k] * W2s[kh + k][c];
    acc += __shfl_down_sync(0xffffffffu, acc, 16);
    if (lane < 16) hw[(size_t)w * F2 + c] = acc;
}

// ---------------- gather-reduce F=16 (fp32) ----------------
__global__ void gather16(const float* __restrict__ src, float* __restrict__ dst,
                         const int* __restrict__ mem, const int* __restrict__ off,
                         const float* __restrict__ inv, const float* __restrict__ bias,
                         int nrows) {
    int w = (blockIdx.x * blockDim.x + threadIdx.x) >> 5;
    int lane = threadIdx.x & 31;
    if (w >= nrows) return;
    int beg = off[w], end = off[w + 1];
    int half = lane >> 4, f = lane & 15;
    float acc = 0.f;
    for (int j = beg + half; j < end; j += 2)
        acc += src[(size_t)mem[j] * F2 + f];
    acc += __shfl_down_sync(0xffffffffu, acc, 16);
    if (lane < 16) {
        float r = acc * inv[w];
        if (bias) r += bias[f];
        dst[(size_t)w * F2 + f] = r;
    }
}

// ---------------- launcher ----------------
extern "C" void kernel_launch(void* const* d_in, const int* in_sizes, int n_in,
                              void* d_out, int out_size) {
    const float* x  = (const float*)d_in[0];
    const void*  ni = d_in[1];
    const void*  ei = d_in[2];
    const float* W1 = (const float*)d_in[n_in - 4];
    const float* b1 = (const float*)d_in[n_in - 3];
    const float* W2 = (const float*)d_in[n_in - 2];
    const float* b2 = (const float*)d_in[n_in - 1];
    const int nnz = in_sizes[1];
    const int M   = in_sizes[0] / F1;   // nodes
    float* out = (float*)d_out;

    static bool  s_init = false;
    static cudaStream_t s2;
    static cudaEvent_t ev_xh, ev_csr, ev_nfill;
    static int*    p_eoff, *p_noff, *p_emem, *p_nmem;
    static float*  p_binv, *p_dinv, *p_hw, *p_ef2;
    static __half* p_xh, *p_agg, *p_ef;
    if (!s_init) {
        cudaGetSymbolAddress((void**)&p_eoff, g_eoff);
        cudaGetSymbolAddress((void**)&p_noff, g_noff);
        cudaGetSymbolAddress((void**)&p_emem, g_e_members);
        cudaGetSymbolAddress((void**)&p_nmem, g_n_members);
        cudaGetSymbolAddress((void**)&p_binv, g_binv);
        cudaGetSymbolAddress((void**)&p_dinv, g_dinv);
        cudaGetSymbolAddress((void**)&p_xh,   g_xh);
        cudaGetSymbolAddress((void**)&p_agg,  g_agg);
        cudaGetSymbolAddress((void**)&p_ef,   g_ef);
        cudaGetSymbolAddress((void**)&p_hw,   g_hw);
        cudaGetSymbolAddress((void**)&p_ef2,  g_efeat2);
        cudaStreamCreateWithFlags(&s2, cudaStreamNonBlocking);
        cudaEventCreateWithFlags(&ev_xh,    cudaEventDisableTiming);
        cudaEventCreateWithFlags(&ev_csr,   cudaEventDisableTiming);
        cudaEventCreateWithFlags(&ev_nfill, cudaEventDisableTiming);
        s_init = true;
    }

    // s2: x -> fp16 (hidden under CSR build)
    cudaEventRecord(ev_xh, 0);                  // make s2 wait for graph-entry deps
    cudaStreamWaitEvent(s2, ev_xh, 0);
    int n4 = M * F1 / 4;
    convert_half_kernel<<<(n4 + 255) / 256, 256, 0, s2>>>(x, p_xh, n4);
    cudaEventRecord(ev_xh, s2);

    // default stream: CSR build
    zero_detect_kernel<<<(N_NODES_C + 255) / 256, 256>>>(ni, nnz);
    hist_kernel<<<(nnz + 255) / 256, 256>>>(ni, ei, nnz);
    bsums_kernel<<<NB_E + NB_N, 512>>>();
    scanmid_kernel<<<1, 512>>>();
    apply_kernel<<<NB_E + NB_N, 512>>>();
    cudaEventRecord(ev_csr, 0);

    // s2: node-side fill overlaps edge-side fill + gather1
    cudaStreamWaitEvent(s2, ev_csr, 0);
    fill_n_kernel<<<(nnz + 255) / 256, 256, 0, s2>>>(ni, ei, nnz);
    cudaEventRecord(ev_nfill, s2);

    // default: edge-side fill, then layer-1 node->edge gather of raw x
    fill_e_kernel<<<(nnz + 255) / 256, 256>>>(ni, ei, nnz);
    cudaStreamWaitEvent(0, ev_xh, 0);
    int blocks_e = (N_EDGES_C * 32 + 255) / 256;
    int blocks_n = (N_NODES_C * 32 + 255) / 256;
    gather128h<<<blocks_e, 256>>>(p_xh, p_agg, p_emem, p_eoff, p_binv, N_EDGES_C);

    // edge-level GEMM: ef = agg @ W1   (half the FLOPs of node-level GEMM)
    gemm_e_f16<<<(N_EDGES_C + 127) / 128, 512>>>(p_agg, W1, p_ef, N_EDGES_C);

    // layer-1 edge->node gather (Dinv, +b1, relu) fused with @W2
    cudaStreamWaitEvent(0, ev_nfill, 0);
    gather128h_w2<<<blocks_n, 256>>>(p_ef, p_nmem, p_noff, p_dinv, b1, W2, p_hw, N_NODES_C);

    // layer 2
    gather16<<<blocks_e, 256>>>(p_hw,  p_ef2, p_emem, p_eoff, p_binv, nullptr, N_EDGES_C);
    gather16<<<blocks_n, 256>>>(p_ef2, out,   p_nmem, p_noff, p_dinv, b2,      N_NODES_C);
}

// round 7
// speedup vs baseline: 2.0452x; 1.0471x over previous
#include <cuda_runtime.h>
#include <cuda_fp16.h>

#define N_NODES_C 100000
#define N_EDGES_C 50000
#define NNZ_CAP   1600000
#define F1 128
#define F2 16
#define NB_E ((N_EDGES_C + 511) / 512)   // 98
#define NB_N ((N_NODES_C + 511) / 512)   // 196

// ---------------- static scratch (no cudaMalloc anywhere) ----------------
__device__ int   g_idx64;
__device__ int   g_ncnt[N_NODES_C];
__device__ int   g_ecnt[N_EDGES_C];
__device__ int   g_noff[N_NODES_C + 1];
__device__ int   g_eoff[N_EDGES_C + 1];
__device__ int   g_bse[NB_E];
__device__ int   g_bsn[NB_N];
__device__ float g_dinv[N_NODES_C];
__device__ float g_binv[N_EDGES_C];
__device__ int   g_ni32[NNZ_CAP];
__device__ int   g_ei32[NNZ_CAP];
__device__ int   g_rank_n[NNZ_CAP];
__device__ int   g_rank_e[NNZ_CAP];
__device__ int   g_e_members[NNZ_CAP];                            // node ids grouped by edge
__device__ int   g_n_members[NNZ_CAP];                            // edge ids grouped by node
__device__ __align__(16) __half g_xh[(size_t)N_NODES_C * F1];     // x in fp16
__device__ __align__(16) __half g_w1h[F1 * F1];                   // W1 hi, [n][k]
__device__ __align__(16) __half g_w1l[F1 * F1];                   // W1 lo, [n][k]
__device__ __align__(16) __half g_xw[(size_t)N_NODES_C * F1];     // x @ W1, fp16
__device__ __align__(16) __half g_ef[(size_t)N_EDGES_C * F1];     // Binv*segsum(xw)
__device__ __align__(16) float  g_hw[(size_t)N_NODES_C * F2];
__device__ __align__(16) float  g_efeat2[(size_t)N_EDGES_C * F2];

__device__ __forceinline__ int load_idx(const void* p, int i, int is64) {
    return is64 ? (int)((const long long*)p)[i] : ((const int*)p)[i];
}

// ---------------- s2 chain: x -> fp16, W1 -> hi/lo fp16 (transposed) ----------------
__global__ void convert_half_kernel(const float* __restrict__ x,
                                    __half* __restrict__ xh, int n4) {
    int i = blockIdx.x * blockDim.x + threadIdx.x;
    if (i < n4) {
        float4 v = ((const float4*)x)[i];
        uint2 o;
        *(__half2*)&o.x = __floats2half2_rn(v.x, v.y);
        *(__half2*)&o.y = __floats2half2_rn(v.z, v.w);
        ((uint2*)xh)[i] = o;
    }
}

__global__ void split_w1_kernel(const float* __restrict__ W) {
    int i = blockIdx.x * blockDim.x + threadIdx.x;
    if (i < F1 * F1) {
        int k = i >> 7, n = i & 127;       // W[k][n] row-major
        float w = W[i];
        __half hi = __float2half_rn(w);
        __half lo = __float2half_rn(w - __half2float(hi));
        g_w1h[n * F1 + k] = hi;            // store transposed [n][k]
        g_w1l[n * F1 + k] = lo;
    }
}

// ---------------- zero counters + detect index dtype (fused) ----------------
__global__ void zero_detect_kernel(const void* ni, int nnz) {
    __shared__ int bad_s;
    int i = blockIdx.x * blockDim.x + threadIdx.x;
    if (i < N_NODES_C) g_ncnt[i] = 0;
    if (i < N_EDGES_C) g_ecnt[i] = 0;
    if (blockIdx.x == 0) {
        if (threadIdx.x == 0) bad_s = 0;
        __syncthreads();
        int k = nnz < 64 ? nnz : 64;
        if ((int)threadIdx.x < k) {
            long long v = ((const long long*)ni)[threadIdx.x];
            if (v < 0 || v >= (1LL << 31)) atomicOr(&bad_s, 1);
        }
        __syncthreads();
        if (threadIdx.x == 0) g_idx64 = bad_s ? 0 : 1;
    }
}

// ---------------- histogram + rank + int32 index copies ----------------
__global__ void hist_rank_kernel(const void* ni, const void* ei, int nnz) {
    int i = blockIdx.x * blockDim.x + threadIdx.x;
    if (i >= nnz) return;
    int is64 = g_idx64;
    int n = load_idx(ni, i, is64);
    int e = load_idx(ei, i, is64);
    g_ni32[i] = n;
    g_ei32[i] = e;
    g_rank_n[i] = atomicAdd(&g_ncnt[n], 1);
    g_rank_e[i] = atomicAdd(&g_ecnt[e], 1);
}

// ---------------- coalesced 3-phase scan, edges+nodes in one grid ----------------
__global__ __launch_bounds__(512) void bsums_kernel() {
    __shared__ int s[512];
    const bool edges = blockIdx.x < NB_E;
    const int  b   = edges ? blockIdx.x : blockIdx.x - NB_E;
    const int* cnt = edges ? g_ecnt : g_ncnt;
    const int  n   = edges ? N_EDGES_C : N_NODES_C;
    int i = b * 512 + threadIdx.x;
    s[threadIdx.x] = (i < n) ? cnt[i] : 0;
    __syncthreads();
    for (int d = 256; d > 0; d >>= 1) {
        if ((int)threadIdx.x < d) s[threadIdx.x] += s[threadIdx.x + d];
        __syncthreads();
    }
    if (threadIdx.x == 0) (edges ? g_bse : g_bsn)[b] = s[0];
}

__global__ __launch_bounds__(512) void scanmid_kernel() {
    __shared__ int s[512];
    const int tid = threadIdx.x;
    for (int pass = 0; pass < 2; pass++) {
        int* b = pass ? g_bsn : g_bse;
        int nb = pass ? NB_N : NB_E;
        int v = (tid < nb) ? b[tid] : 0;
        s[tid] = v;
        __syncthreads();
        for (int d = 1; d < 512; d <<= 1) {
            int t = (tid >= d) ? s[tid - d] : 0;
            __syncthreads();
            s[tid] += t;
            __syncthreads();
        }
        if (tid < nb) b[tid] = s[tid] - v;
        __syncthreads();
    }
}

__global__ __launch_bounds__(512) void apply_kernel() {
    __shared__ int s[512];
    const int tid = threadIdx.x;
    const bool edges = blockIdx.x < NB_E;
    const int  b   = edges ? blockIdx.x : blockIdx.x - NB_E;
    const int* cnt = edges ? g_ecnt : g_ncnt;
    int*   off = edges ? g_eoff : g_noff;
    float* inv = edges ? g_binv : g_dinv;
    const int n = edges ? N_EDGES_C : N_NODES_C;
    int i = b * 512 + tid;
    int v = (i < n) ? cnt[i] : 0;
    s[tid] = v;
    __syncthreads();
    for (int d = 1; d < 512; d <<= 1) {
        int t = (tid >= d) ? s[tid - d] : 0;
        __syncthreads();
        s[tid] += t;
        __syncthreads();
    }
    int base = (edges ? g_bse : g_bsn)[b];
    if (i < n) {
        off[i] = base + s[tid] - v;
        inv[i] = v > 0 ? 1.f / (float)v : 0.f;
        if (i == n - 1) off[n] = base + s[tid];
    }
}

// ---------------- atomic-free fill: both member lists in one pass ----------------
__global__ void fill_kernel(int nnz) {
    int i = blockIdx.x * blockDim.x + threadIdx.x;
    if (i >= nnz) return;
    int n = g_ni32[i];
    int e = g_ei32[i];
    g_e_members[g_eoff[e] + g_rank_e[i]] = n;
    g_n_members[g_noff[n] + g_rank_n[i]] = e;
}

// ---------------- node-level GEMM: xh [M,128] fp16 @ W1 (pre-split hi/lo) -> xw fp16
// 2-pass fp16 m16n8k16; A exact fp16, W1 error ~2^-22.
__device__ __forceinline__ void mma_f16(float* c, unsigned a0, unsigned a1,
                                        unsigned a2, unsigned a3,
                                        unsigned b0, unsigned b1) {
    asm("mma.sync.aligned.m16n8k16.row.col.f32.f16.f16.f32 "
        "{%0,%1,%2,%3}, {%4,%5,%6,%7}, {%8,%9}, {%0,%1,%2,%3};"
        : "+f"(c[0]), "+f"(c[1]), "+f"(c[2]), "+f"(c[3])
        : "r"(a0), "r"(a1), "r"(a2), "r"(a3), "r"(b0), "r"(b1));
}

__global__ __launch_bounds__(512) void gemm1_f16(const __half* __restrict__ A,
                                                 __half* __restrict__ out, int M) {
    __shared__ __half As[128][40];          // [m][k-chunk], pad 40
    __shared__ __half Bh[128][40];          // [n][k-chunk], hi
    __shared__ __half Bl[128][40];          // lo
    const int tid = threadIdx.x;
    const int wid = tid >> 5, lane = tid & 31;
    const int g = lane >> 2, t = lane & 3;
    const int wm = (wid >> 2) * 32, wn = (wid & 3) * 32;
    const int mbase = blockIdx.x * 128;

    float acc[2][4][4];
#pragma unroll
    for (int a = 0; a < 2; a++)
#pragma unroll
        for (int b = 0; b < 4; b++)
#pragma unroll
            for (int c = 0; c < 4; c++) acc[a][b][c] = 0.f;

    for (int kc = 0; kc < 128; kc += 32) {
#pragma unroll
        for (int i = 0; i < 2; i++) {
            int idx = tid + i * 512;             // 0..1023
            int r = idx >> 3, q = idx & 7;
            int row = mbase + r;
            uint2 v = (row < M) ? *(const uint2*)&A[(size_t)row * 128 + kc + q * 4]
                                : make_uint2(0u, 0u);
            *(uint2*)&As[r][q * 4] = v;
            *(uint2*)&Bh[r][q * 4] = *(const uint2*)&g_w1h[r * 128 + kc + q * 4];
            *(uint2*)&Bl[r][q * 4] = *(const uint2*)&g_w1l[r * 128 + kc + q * 4];
        }
        __syncthreads();

#pragma unroll
        for (int ks = 0; ks < 2; ks++) {
            const int k0 = ks * 16;
#pragma unroll
            for (int mt = 0; mt < 2; mt++) {
                const int rm = wm + mt * 16;
                unsigned a0 = *(unsigned*)&As[rm + g][k0 + 2 * t];
                unsigned a1 = *(unsigned*)&As[rm + g + 8][k0 + 2 * t];
                unsigned a2 = *(unsigned*)&As[rm + g][k0 + 2 * t + 8];
                unsigned a3 = *(unsigned*)&As[rm + g + 8][k0 + 2 * t + 8];
#pragma unroll
                for (int nt = 0; nt < 4; nt++) {
                    int n = wn + nt * 8 + g;
                    unsigned bh0 = *(unsigned*)&Bh[n][k0 + 2 * t];
                    unsigned bh1 = *(unsigned*)&Bh[n][k0 + 2 * t + 8];
                    unsigned bl0 = *(unsigned*)&Bl[n][k0 + 2 * t];
                    unsigned bl1 = *(unsigned*)&Bl[n][k0 + 2 * t + 8];
                    mma_f16(acc[mt][nt], a0, a1, a2, a3, bh0, bh1);
                    mma_f16(acc[mt][nt], a0, a1, a2, a3, bl0, bl1);
                }
            }
        }
        __syncthreads();
    }

#pragma unroll
    for (int mt = 0; mt < 2; mt++) {
#pragma unroll
        for (int nt = 0; nt < 4; nt++) {
            int row = mbase + wm + mt * 16 + g;
            int col = wn + nt * 8 + 2 * t;
            if (row < M)
                *(__half2*)&out[(size_t)row * 128 + col] =
                    __floats2half2_rn(acc[mt][nt][0], acc[mt][nt][1]);
            if (row + 8 < M)
                *(__half2*)&out[(size_t)(row + 8) * 128 + col] =
                    __floats2half2_rn(acc[mt][nt][2], acc[mt][nt][3]);
        }
    }
}

// ---------------- gather-reduce F=128 fp16 (warp per row) ----------------
__device__ __forceinline__ void acc_h4(float4& a, uint2 raw) {
    float2 f01 = __half22float2(*(__half2*)&raw.x);
    float2 f23 = __half22float2(*(__half2*)&raw.y);
    a.x += f01.x; a.y += f01.y; a.z += f23.x; a.w += f23.y;
}

__global__ __launch_bounds__(256) void gather128h(const __half* __restrict__ src,
                                                  __half* __restrict__ dst,
                                                  const int* __restrict__ mem,
                                                  const int* __restrict__ off,
                                                  const float* __restrict__ inv,
                                                  int nrows) {
    int w = (blockIdx.x * blockDim.x + threadIdx.x) >> 5;
    int lane = threadIdx.x & 31;
    if (w >= nrows) return;
    int beg = off[w], end = off[w + 1];
    float4 a = make_float4(0.f, 0.f, 0.f, 0.f);
    int j = beg;
    for (; j + 3 < end; j += 4) {
        int m0 = mem[j], m1 = mem[j + 1], m2 = mem[j + 2], m3 = mem[j + 3];
        uint2 r0 = *(const uint2*)&src[(size_t)m0 * F1 + lane * 4];
        uint2 r1 = *(const uint2*)&src[(size_t)m1 * F1 + lane * 4];
        uint2 r2 = *(const uint2*)&src[(size_t)m2 * F1 + lane * 4];
        uint2 r3 = *(const uint2*)&src[(size_t)m3 * F1 + lane * 4];
        acc_h4(a, r0); acc_h4(a, r1); acc_h4(a, r2); acc_h4(a, r3);
    }
    for (; j < end; j++) {
        uint2 r0 = *(const uint2*)&src[(size_t)mem[j] * F1 + lane * 4];
        acc_h4(a, r0);
    }
    float s = inv[w];
    uint2 o;
    *(__half2*)&o.x = __floats2half2_rn(a.x * s, a.y * s);
    *(__half2*)&o.y = __floats2half2_rn(a.z * s, a.w * s);
    *(uint2*)&dst[(size_t)w * F1 + lane * 4] = o;
}

// ------- gather-reduce F=128 fp16 + bias + relu + fused [128x16] W2 multiply -------
__global__ __launch_bounds__(256) void gather128h_w2(const __half* __restrict__ src,
                                                     const int* __restrict__ mem,
                                                     const int* __restrict__ off,
                                                     const float* __restrict__ inv,
                                                     const float* __restrict__ bias,
                                                     const float* __restrict__ W2,
                                                     float* __restrict__ hw, int nrows) {
    __shared__ float W2s[128][17];
    __shared__ float hs[8][128];
    const int tid = threadIdx.x;
    for (int i = tid; i < 128 * 16; i += 256) W2s[i >> 4][i & 15] = W2[i];
    __syncthreads();

    int w = (blockIdx.x * blockDim.x + tid) >> 5;
    int lane = tid & 31, wl = tid >> 5;
    if (w >= nrows) return;
    int beg = off[w], end = off[w + 1];
    float4 a = make_float4(0.f, 0.f, 0.f, 0.f);
    int j = beg;
    for (; j + 3 < end; j += 4) {
        int m0 = mem[j], m1 = mem[j + 1], m2 = mem[j + 2], m3 = mem[j + 3];
        uint2 r0 = *(const uint2*)&src[(size_t)m0 * F1 + lane * 4];
        uint2 r1 = *(const uint2*)&src[(size_t)m1 * F1 + lane * 4];
        uint2 r2 = *(const uint2*)&src[(size_t)m2 * F1 + lane * 4];
        uint2 r3 = *(const uint2*)&src[(size_t)m3 * F1 + lane * 4];
        acc_h4(a, r0); acc_h4(a, r1); acc_h4(a, r2); acc_h4(a, r3);
    }
    for (; j < end; j++) {
        uint2 r0 = *(const uint2*)&src[(size_t)mem[j] * F1 + lane * 4];
        acc_h4(a, r0);
    }
    float s = inv[w];
    float4 b = *(const float4*)&bias[lane * 4];
    hs[wl][lane * 4 + 0] = fmaxf(a.x * s + b.x, 0.f);
    hs[wl][lane * 4 + 1] = fmaxf(a.y * s + b.y, 0.f);
    hs[wl][lane * 4 + 2] = fmaxf(a.z * s + b.z, 0.f);
    hs[wl][lane * 4 + 3] = fmaxf(a.w * s + b.w, 0.f);
    __syncwarp();

    const int c = lane & 15, kh = (lane >> 4) * 64;
    float acc = 0.f;
#pragma unroll 8
    for (int k = 0; k < 64; k++) acc += hs[wl][kh + k] * W2s[kh + k][c];
    acc += __shfl_down_sync(0xffffffffu, acc, 16);
    if (lane < 16) hw[(size_t)w * F2 + c] = acc;
}

// ---------------- gather-reduce F=16 (fp32) ----------------
__global__ void gather16(const float* __restrict__ src, float* __restrict__ dst,
                         const int* __restrict__ mem, const int* __restrict__ off,
                         const float* __restrict__ inv, const float* __restrict__ bias,
                         int nrows) {
    int w = (blockIdx.x * blockDim.x + threadIdx.x) >> 5;
    int lane = threadIdx.x & 31;
    if (w >= nrows) return;
    int beg = off[w], end = off[w + 1];
    int half = lane >> 4, f = lane & 15;
    float acc = 0.f;
    for (int j = beg + half; j < end; j += 2)
        acc += src[(size_t)mem[j] * F2 + f];
    acc += __shfl_down_sync(0xffffffffu, acc, 16);
    if (lane < 16) {
        float r = acc * inv[w];
        if (bias) r += bias[f];
        dst[(size_t)w * F2 + f] = r;
    }
}

// ---------------- launcher ----------------
extern "C" void kernel_launch(void* const* d_in, const int* in_sizes, int n_in,
                              void* d_out, int out_size) {
    const float* x  = (const float*)d_in[0];
    const void*  ni = d_in[1];
    const void*  ei = d_in[2];
    const float* W1 = (const float*)d_in[n_in - 4];
    const float* b1 = (const float*)d_in[n_in - 3];
    const float* W2 = (const float*)d_in[n_in - 2];
    const float* b2 = (const float*)d_in[n_in - 1];
    const int nnz = in_sizes[1];
    const int M   = in_sizes[0] / F1;   // nodes
    float* out = (float*)d_out;

    static bool  s_init = false;
    static cudaStream_t s2;
    static cudaEvent_t ev_fork, ev_gemm;
    static int*    p_eoff, *p_noff, *p_emem, *p_nmem;
    static float*  p_binv, *p_dinv, *p_hw, *p_ef2;
    static __half* p_xh, *p_xw, *p_ef;
    if (!s_init) {
        cudaGetSymbolAddress((void**)&p_eoff, g_eoff);
        cudaGetSymbolAddress((void**)&p_noff, g_noff);
        cudaGetSymbolAddress((void**)&p_emem, g_e_members);
        cudaGetSymbolAddress((void**)&p_nmem, g_n_members);
        cudaGetSymbolAddress((void**)&p_binv, g_binv);
        cudaGetSymbolAddress((void**)&p_dinv, g_dinv);
        cudaGetSymbolAddress((void**)&p_xh,   g_xh);
        cudaGetSymbolAddress((void**)&p_xw,   g_xw);
        cudaGetSymbolAddress((void**)&p_ef,   g_ef);
        cudaGetSymbolAddress((void**)&p_hw,   g_hw);
        cudaGetSymbolAddress((void**)&p_ef2,  g_efeat2);
        cudaStreamCreateWithFlags(&s2, cudaStreamNonBlocking);
        cudaEventCreateWithFlags(&ev_fork, cudaEventDisableTiming);
        cudaEventCreateWithFlags(&ev_gemm, cudaEventDisableTiming);
        s_init = true;
    }

    // ---- fork: convert + W1 split + node-level GEMM on s2, hidden under CSR build
    cudaEventRecord(ev_fork, 0);
    cudaStreamWaitEvent(s2, ev_fork, 0);
    int n4 = M * F1 / 4;
    convert_half_kernel<<<(n4 + 255) / 256, 256, 0, s2>>>(x, p_xh, n4);
    split_w1_kernel<<<(F1 * F1 + 255) / 256, 256, 0, s2>>>(W1);
    gemm1_f16<<<(M + 127) / 128, 512, 0, s2>>>(p_xh, p_xw, M);
    cudaEventRecord(ev_gemm, s2);

    // ---- default stream: CSR build (rank-based, single atomic pass)
    zero_detect_kernel<<<(N_NODES_C + 255) / 256, 256>>>(ni, nnz);
    hist_rank_kernel<<<(nnz + 255) / 256, 256>>>(ni, ei, nnz);
    bsums_kernel<<<NB_E + NB_N, 512>>>();
    scanmid_kernel<<<1, 512>>>();
    apply_kernel<<<NB_E + NB_N, 512>>>();
    fill_kernel<<<(nnz + 255) / 256, 256>>>(nnz);

    cudaStreamWaitEvent(0, ev_gemm, 0);   // join: gathers need xw

    // layer 1: node->edge gather of xw (Binv), then edge->node (Dinv,+b1,relu) @W2
    int blocks_e = (N_EDGES_C * 32 + 255) / 256;
    int blocks_n = (N_NODES_C * 32 + 255) / 256;
    gather128h<<<blocks_e, 256>>>(p_xw, p_ef, p_emem, p_eoff, p_binv, N_EDGES_C);
    gather128h_w2<<<blocks_n, 256>>>(p_ef, p_nmem, p_noff, p_dinv, b1, W2, p_hw, N_NODES_C);

    // layer 2
    gather16<<<blocks_e, 256>>>(p_hw,  p_ef2, p_emem, p_eoff, p_binv, nullptr, N_EDGES_C);
    gather16<<<blocks_n, 256>>>(p_ef2, out,   p_nmem, p_noff, p_dinv, b2,      N_NODES_C);
}

// round 8
// speedup vs baseline: 2.1792x; 1.0655x over previous
#include <cuda_runtime.h>
#include <cuda_fp16.h>

#define N_NODES_C 100000
#define N_EDGES_C 50000
#define NNZ_CAP   1600000
#define F1 128
#define F2 16
#define NB_E ((N_EDGES_C + 511) / 512)   // 98
#define NB_N ((N_NODES_C + 511) / 512)   // 196

// ---------------- static scratch (no cudaMalloc anywhere) ----------------
__device__ int   g_idx64;
__device__ int   g_ncnt[N_NODES_C];
__device__ int   g_ecnt[N_EDGES_C];
__device__ int   g_noff[N_NODES_C + 1];
__device__ int   g_eoff[N_EDGES_C + 1];
__device__ int   g_bse[NB_E];
__device__ int   g_bsn[NB_N];
__device__ float g_dinv[N_NODES_C];
__device__ float g_binv[N_EDGES_C];
__device__ int   g_ni32[NNZ_CAP];
__device__ int   g_ei32[NNZ_CAP];
__device__ int   g_rank_n[NNZ_CAP];
__device__ int   g_rank_e[NNZ_CAP];
__device__ int   g_e_members[NNZ_CAP];                            // node ids grouped by edge
__device__ int   g_n_members[NNZ_CAP];                            // edge ids grouped by node
__device__ __align__(16) __half g_w1h[F1 * F1];                   // W1 hi, [n][k]
__device__ __align__(16) __half g_w1l[F1 * F1];                   // W1 lo, [n][k]
__device__ __align__(16) __half g_xw[(size_t)N_NODES_C * F1];     // x @ W1, fp16
__device__ __align__(16) __half g_ef[(size_t)N_EDGES_C * F1];     // Binv*segsum(xw)
__device__ __align__(16) float  g_hw[(size_t)N_NODES_C * F2];
__device__ __align__(16) float  g_efeat2[(size_t)N_EDGES_C * F2];

__device__ __forceinline__ int load_idx(const void* p, int i, int is64) {
    return is64 ? (int)((const long long*)p)[i] : ((const int*)p)[i];
}

// ---------------- W1 -> fp16 hi/lo, transposed (s2) ----------------
__global__ void split_w1_kernel(const float* __restrict__ W) {
    int i = blockIdx.x * blockDim.x + threadIdx.x;
    if (i < F1 * F1) {
        int k = i >> 7, n = i & 127;       // W[k][n] row-major
        float w = W[i];
        __half hi = __float2half_rn(w);
        __half lo = __float2half_rn(w - __half2float(hi));
        g_w1h[n * F1 + k] = hi;            // store transposed [n][k]
        g_w1l[n * F1 + k] = lo;
    }
}

// ---------------- zero counters (int4) + detect index dtype ----------------
__global__ void zero_detect_kernel(const void* ni, int nnz) {
    __shared__ int bad_s;
    int i = blockIdx.x * blockDim.x + threadIdx.x;
    int4 z = make_int4(0, 0, 0, 0);
    if (i < N_NODES_C / 4) ((int4*)g_ncnt)[i] = z;
    if (i < N_EDGES_C / 4) ((int4*)g_ecnt)[i] = z;
    if (blockIdx.x == 0) {
        if (threadIdx.x == 0) bad_s = 0;
        __syncthreads();
        int k = nnz < 64 ? nnz : 64;
        if ((int)threadIdx.x < k) {
            long long v = ((const long long*)ni)[threadIdx.x];
            if (v < 0 || v >= (1LL << 31)) atomicOr(&bad_s, 1);
        }
        __syncthreads();
        if (threadIdx.x == 0) g_idx64 = bad_s ? 0 : 1;
    }
}

// ---------------- per-side CSR kernels (pointer-parameterized) ----------------
__global__ void hist_side_kernel(const void* idx, int* __restrict__ idx32,
                                 int* __restrict__ rank, int* __restrict__ cnt, int nnz) {
    int i = blockIdx.x * blockDim.x + threadIdx.x;
    if (i >= nnz) return;
    int v = load_idx(idx, i, g_idx64);
    idx32[i] = v;
    rank[i] = atomicAdd(&cnt[v], 1);
}

__global__ __launch_bounds__(512) void bsums_side_kernel(const int* __restrict__ cnt,
                                                         int n, int* __restrict__ bs) {
    __shared__ int s[512];
    int i = blockIdx.x * 512 + threadIdx.x;
    s[threadIdx.x] = (i < n) ? cnt[i] : 0;
    __syncthreads();
    for (int d = 256; d > 0; d >>= 1) {
        if ((int)threadIdx.x < d) s[threadIdx.x] += s[threadIdx.x + d];
        __syncthreads();
    }
    if (threadIdx.x == 0) bs[blockIdx.x] = s[0];
}

__global__ __launch_bounds__(512) void scanmid_side_kernel(int* __restrict__ bs, int nb) {
    __shared__ int s[512];
    const int tid = threadIdx.x;
    int v = (tid < nb) ? bs[tid] : 0;
    s[tid] = v;
    __syncthreads();
    for (int d = 1; d < 512; d <<= 1) {
        int t = (tid >= d) ? s[tid - d] : 0;
        __syncthreads();
        s[tid] += t;
        __syncthreads();
    }
    if (tid < nb) bs[tid] = s[tid] - v;   // exclusive
}

__global__ __launch_bounds__(512) void apply_side_kernel(const int* __restrict__ cnt, int n,
                                                         const int* __restrict__ bs,
                                                         int* __restrict__ off,
                                                         float* __restrict__ inv) {
    __shared__ int s[512];
    const int tid = threadIdx.x;
    int i = blockIdx.x * 512 + tid;
    int v = (i < n) ? cnt[i] : 0;
    s[tid] = v;
    __syncthreads();
    for (int d = 1; d < 512; d <<= 1) {
        int t = (tid >= d) ? s[tid - d] : 0;
        __syncthreads();
        s[tid] += t;
        __syncthreads();
    }
    int base = bs[blockIdx.x];
    if (i < n) {
        off[i] = base + s[tid] - v;
        inv[i] = v > 0 ? 1.f / (float)v : 0.f;
        if (i == n - 1) off[n] = base + s[tid];
    }
}

// atomic-free fill: members[off[own]+rank] = other-side id (read from original array)
__global__ void fill_side_kernel(const int* __restrict__ idx32, const int* __restrict__ rank,
                                 const int* __restrict__ off, const void* other,
                                 int* __restrict__ members, int nnz) {
    int i = blockIdx.x * blockDim.x + threadIdx.x;
    if (i >= nnz) return;
    members[off[idx32[i]] + rank[i]] = load_idx(other, i, g_idx64);
}

// ---------------- node-level GEMM: x [M,128] fp32 @ W1 (pre-split hi/lo) -> xw fp16
// convert-in-kernel; 2-pass fp16 m16n8k16 (error ~2^-22 on W1, A fp16-rounded once)
__device__ __forceinline__ void mma_f16(float* c, unsigned a0, unsigned a1,
                                        unsigned a2, unsigned a3,
                                        unsigned b0, unsigned b1) {
    asm("mma.sync.aligned.m16n8k16.row.col.f32.f16.f16.f32 "
        "{%0,%1,%2,%3}, {%4,%5,%6,%7}, {%8,%9}, {%0,%1,%2,%3};"
        : "+f"(c[0]), "+f"(c[1]), "+f"(c[2]), "+f"(c[3])
        : "r"(a0), "r"(a1), "r"(a2), "r"(a3), "r"(b0), "r"(b1));
}

__global__ __launch_bounds__(512) void gemm1_f16(const float* __restrict__ A,
                                                 __half* __restrict__ out, int M) {
    __shared__ __half As[128][40];          // [m][k-chunk], pad 40
    __shared__ __half Bh[128][40];          // [n][k-chunk], hi
    __shared__ __half Bl[128][40];          // lo
    const int tid = threadIdx.x;
    const int wid = tid >> 5, lane = tid & 31;
    const int g = lane >> 2, t = lane & 3;
    const int wm = (wid >> 2) * 32, wn = (wid & 3) * 32;
    const int mbase = blockIdx.x * 128;

    float acc[2][4][4];
#pragma unroll
    for (int a = 0; a < 2; a++)
#pragma unroll
        for (int b = 0; b < 4; b++)
#pragma unroll
            for (int c = 0; c < 4; c++) acc[a][b][c] = 0.f;

    for (int kc = 0; kc < 128; kc += 32) {
#pragma unroll
        for (int i = 0; i < 2; i++) {
            int idx = tid + i * 512;             // 0..1023
            int r = idx >> 3, q = idx & 7;       // 8 float4 per 32-float row chunk
            int row = mbase + r;
            float4 v = (row < M) ? *(const float4*)&A[(size_t)row * 128 + kc + q * 4]
                                 : make_float4(0.f, 0.f, 0.f, 0.f);
            uint2 h;
            *(__half2*)&h.x = __floats2half2_rn(v.x, v.y);
            *(__half2*)&h.y = __floats2half2_rn(v.z, v.w);
            *(uint2*)&As[r][q * 4] = h;
            *(uint2*)&Bh[r][q * 4] = *(const uint2*)&g_w1h[r * 128 + kc + q * 4];
            *(uint2*)&Bl[r][q * 4] = *(const uint2*)&g_w1l[r * 128 + kc + q * 4];
        }
        __syncthreads();

#pragma unroll
        for (int ks = 0; ks < 2; ks++) {
            const int k0 = ks * 16;
#pragma unroll
            for (int mt = 0; mt < 2; mt++) {
                const int rm = wm + mt * 16;
                unsigned a0 = *(unsigned*)&As[rm + g][k0 + 2 * t];
                unsigned a1 = *(unsigned*)&As[rm + g + 8][k0 + 2 * t];
                unsigned a2 = *(unsigned*)&As[rm + g][k0 + 2 * t + 8];
                unsigned a3 = *(unsigned*)&As[rm + g + 8][k0 + 2 * t + 8];
#pragma unroll
                for (int nt = 0; nt < 4; nt++) {
                    int n = wn + nt * 8 + g;
                    unsigned bh0 = *(unsigned*)&Bh[n][k0 + 2 * t];
                    unsigned bh1 = *(unsigned*)&Bh[n][k0 + 2 * t + 8];
                    unsigned bl0 = *(unsigned*)&Bl[n][k0 + 2 * t];
                    unsigned bl1 = *(unsigned*)&Bl[n][k0 + 2 * t + 8];
                    mma_f16(acc[mt][nt], a0, a1, a2, a3, bh0, bh1);
                    mma_f16(acc[mt][nt], a0, a1, a2, a3, bl0, bl1);
                }
            }
        }
        __syncthreads();
    }

#pragma unroll
    for (int mt = 0; mt < 2; mt++) {
#pragma unroll
        for (int nt = 0; nt < 4; nt++) {
            int row = mbase + wm + mt * 16 + g;
            int col = wn + nt * 8 + 2 * t;
            if (row < M)
                *(__half2*)&out[(size_t)row * 128 + col] =
                    __floats2half2_rn(acc[mt][nt][0], acc[mt][nt][1]);
            if (row + 8 < M)
                *(__half2*)&out[(size_t)(row + 8) * 128 + col] =
                    __floats2half2_rn(acc[mt][nt][2], acc[mt][nt][3]);
        }
    }
}

// ---------------- gather-reduce F=128 fp16 (warp per row) ----------------
__device__ __forceinline__ void acc_h4(float4& a, uint2 raw) {
    float2 f01 = __half22float2(*(__half2*)&raw.x);
    float2 f23 = __half22float2(*(__half2*)&raw.y);
    a.x += f01.x; a.y += f01.y; a.z += f23.x; a.w += f23.y;
}

__global__ __launch_bounds__(256) void gather128h(const __half* __restrict__ src,
                                                  __half* __restrict__ dst,
                                                  const int* __restrict__ mem,
                                                  const int* __restrict__ off,
                                                  const float* __restrict__ inv,
                                                  int nrows) {
    int w = (blockIdx.x * blockDim.x + threadIdx.x) >> 5;
    int lane = threadIdx.x & 31;
    if (w >= nrows) return;
    int beg = off[w], end = off[w + 1];
    float4 a = make_float4(0.f, 0.f, 0.f, 0.f);
    int j = beg;
    for (; j + 3 < end; j += 4) {
        int m0 = mem[j], m1 = mem[j + 1], m2 = mem[j + 2], m3 = mem[j + 3];
        uint2 r0 = *(const uint2*)&src[(size_t)m0 * F1 + lane * 4];
        uint2 r1 = *(const uint2*)&src[(size_t)m1 * F1 + lane * 4];
        uint2 r2 = *(const uint2*)&src[(size_t)m2 * F1 + lane * 4];
        uint2 r3 = *(const uint2*)&src[(size_t)m3 * F1 + lane * 4];
        acc_h4(a, r0); acc_h4(a, r1); acc_h4(a, r2); acc_h4(a, r3);
    }
    for (; j < end; j++) {
        uint2 r0 = *(const uint2*)&src[(size_t)mem[j] * F1 + lane * 4];
        acc_h4(a, r0);
    }
    float s = inv[w];
    uint2 o;
    *(__half2*)&o.x = __floats2half2_rn(a.x * s, a.y * s);
    *(__half2*)&o.y = __floats2half2_rn(a.z * s, a.w * s);
    *(uint2*)&dst[(size_t)w * F1 + lane * 4] = o;
}

// ------- gather-reduce F=128 fp16 + bias + relu + fused [128x16] W2 multiply -------
__global__ __launch_bounds__(256) void gather128h_w2(const __half* __restrict__ src,
                                                     const int* __restrict__ mem,
                                                     const int* __restrict__ off,
                                                     const float* __restrict__ inv,
                                                     const float* __restrict__ bias,
                                                     const float* __restrict__ W2,
                                                     float* __restrict__ hw, int nrows) {
    __shared__ float W2s[128][17];
    __shared__ float hs[8][128];
    const int tid = threadIdx.x;
    for (int i = tid; i < 128 * 16; i += 256) W2s[i >> 4][i & 15] = W2[i];
    __syncthreads();

    int w = (blockIdx.x * blockDim.x + tid) >> 5;
    int lane = tid & 31, wl = tid >> 5;
    if (w >= nrows) return;
    int beg = off[w], end = off[w + 1];
    float4 a = make_float4(0.f, 0.f, 0.f, 0.f);
    int j = beg;
    for (; j + 3 < end; j += 4) {
        int m0 = mem[j], m1 = mem[j + 1], m2 = mem[j + 2], m3 = mem[j + 3];
        uint2 r0 = *(const uint2*)&src[(size_t)m0 * F1 + lane * 4];
        uint2 r1 = *(const uint2*)&src[(size_t)m1 * F1 + lane * 4];
        uint2 r2 = *(const uint2*)&src[(size_t)m2 * F1 + lane * 4];
        uint2 r3 = *(const uint2*)&src[(size_t)m3 * F1 + lane * 4];
        acc_h4(a, r0); acc_h4(a, r1); acc_h4(a, r2); acc_h4(a, r3);
    }
    for (; j < end; j++) {
        uint2 r0 = *(const uint2*)&src[(size_t)mem[j] * F1 + lane * 4];
        acc_h4(a, r0);
    }
    float s = inv[w];
    float4 b = *(const float4*)&bias[lane * 4];
    hs[wl][lane * 4 + 0] = fmaxf(a.x * s + b.x, 0.f);
    hs[wl][lane * 4 + 1] = fmaxf(a.y * s + b.y, 0.f);
    hs[wl][lane * 4 + 2] = fmaxf(a.z * s + b.z, 0.f);
    hs[wl][lane * 4 + 3] = fmaxf(a.w * s + b.w, 0.f);
    __syncwarp();

    const int c = lane & 15, kh = (lane >> 4) * 64;
    float acc = 0.f;
#pragma unroll 8
    for (int k = 0; k < 64; k++) acc += hs[wl][kh + k] * W2s[kh + k][c];
    acc += __shfl_down_sync(0xffffffffu, acc, 16);
    if (lane < 16) hw[(size_t)w * F2 + c] = acc;
}

// ---------------- gather-reduce F=16 (fp32) ----------------
__global__ void gather16(const float* __restrict__ src, float* __restrict__ dst,
                         const int* __restrict__ mem, const int* __restrict__ off,
                         const float* __restrict__ inv, const float* __restrict__ bias,
                         int nrows) {
    int w = (blockIdx.x * blockDim.x + threadIdx.x) >> 5;
    int lane = threadIdx.x & 31;
    if (w >= nrows) return;
    int beg = off[w], end = off[w + 1];
    int half = lane >> 4, f = lane & 15;
    float acc = 0.f;
    for (int j = beg + half; j < end; j += 2)
        acc += src[(size_t)mem[j] * F2 + f];
    acc += __shfl_down_sync(0xffffffffu, acc, 16);
    if (lane < 16) {
        float r = acc * inv[w];
        if (bias) r += bias[f];
        dst[(size_t)w * F2 + f] = r;
    }
}

// ---------------- launcher ----------------
extern "C" void kernel_launch(void* const* d_in, const int* in_sizes, int n_in,
                              void* d_out, int out_size) {
    const float* x  = (const float*)d_in[0];
    const void*  ni = d_in[1];
    const void*  ei = d_in[2];
    const float* W1 = (const float*)d_in[n_in - 4];
    const float* b1 = (const float*)d_in[n_in - 3];
    const float* W2 = (const float*)d_in[n_in - 2];
    const float* b2 = (const float*)d_in[n_in - 1];
    const int nnz = in_sizes[1];
    const int M   = in_sizes[0] / F1;   // nodes
    float* out = (float*)d_out;

    static bool  s_init = false;
    static cudaStream_t s2, s3;
    static cudaEvent_t ev_fork, ev_gemm, ev_zero, ev_ncsr;
    static int*    p_eoff, *p_noff, *p_emem, *p_nmem;
    static int*    p_ecnt, *p_ncnt, *p_bse, *p_bsn;
    static int*    p_ni32, *p_ei32, *p_rn, *p_re;
    static float*  p_binv, *p_dinv, *p_hw, *p_ef2;
    static __half* p_xw, *p_ef;
    if (!s_init) {
        cudaGetSymbolAddress((void**)&p_eoff, g_eoff);
        cudaGetSymbolAddress((void**)&p_noff, g_noff);
        cudaGetSymbolAddress((void**)&p_emem, g_e_members);
        cudaGetSymbolAddress((void**)&p_nmem, g_n_members);
        cudaGetSymbolAddress((void**)&p_ecnt, g_ecnt);
        cudaGetSymbolAddress((void**)&p_ncnt, g_ncnt);
        cudaGetSymbolAddress((void**)&p_bse,  g_bse);
        cudaGetSymbolAddress((void**)&p_bsn,  g_bsn);
        cudaGetSymbolAddress((void**)&p_ni32, g_ni32);
        cudaGetSymbolAddress((void**)&p_ei32, g_ei32);
        cudaGetSymbolAddress((void**)&p_rn,   g_rank_n);
        cudaGetSymbolAddress((void**)&p_re,   g_rank_e);
        cudaGetSymbolAddress((void**)&p_binv, g_binv);
        cudaGetSymbolAddress((void**)&p_dinv, g_dinv);
        cudaGetSymbolAddress((void**)&p_xw,   g_xw);
        cudaGetSymbolAddress((void**)&p_ef,   g_ef);
        cudaGetSymbolAddress((void**)&p_hw,   g_hw);
        cudaGetSymbolAddress((void**)&p_ef2,  g_efeat2);
        cudaStreamCreateWithFlags(&s2, cudaStreamNonBlocking);
        cudaStreamCreateWithFlags(&s3, cudaStreamNonBlocking);
        cudaEventCreateWithFlags(&ev_fork, cudaEventDisableTiming);
        cudaEventCreateWithFlags(&ev_gemm, cudaEventDisableTiming);
        cudaEventCreateWithFlags(&ev_zero, cudaEventDisableTiming);
        cudaEventCreateWithFlags(&ev_ncsr, cudaEventDisableTiming);
        s_init = true;
    }

    const int hb = (nnz + 255) / 256;
    const int blocks_e = (N_EDGES_C * 32 + 255) / 256;
    const int blocks_n = (N_NODES_C * 32 + 255) / 256;

    // ---- fork to s2: W1 split + node-level GEMM (hidden under edge CSR)
    cudaEventRecord(ev_fork, 0);
    cudaStreamWaitEvent(s2, ev_fork, 0);
    split_w1_kernel<<<(F1 * F1 + 255) / 256, 256, 0, s2>>>(W1);
    gemm1_f16<<<(M + 127) / 128, 512, 0, s2>>>(x, p_xw, M);
    cudaEventRecord(ev_gemm, s2);

    // ---- s0: zero + detect, then EDGE-side CSR (critical for gather1)
    zero_detect_kernel<<<(N_NODES_C / 4 + 255) / 256, 256>>>(ni, nnz);
    cudaEventRecord(ev_zero, 0);

    // ---- s3: NODE-side CSR (only needed by gather2; overlaps edge CSR + gather1)
    cudaStreamWaitEvent(s3, ev_zero, 0);
    hist_side_kernel<<<hb, 256, 0, s3>>>(ni, p_ni32, p_rn, p_ncnt, nnz);
    bsums_side_kernel<<<NB_N, 512, 0, s3>>>(p_ncnt, N_NODES_C, p_bsn);
    scanmid_side_kernel<<<1, 512, 0, s3>>>(p_bsn, NB_N);
    apply_side_kernel<<<NB_N, 512, 0, s3>>>(p_ncnt, N_NODES_C, p_bsn, p_noff, p_dinv);
    fill_side_kernel<<<hb, 256, 0, s3>>>(p_ni32, p_rn, p_noff, ei, p_nmem, nnz);
    cudaEventRecord(ev_ncsr, s3);

    // ---- s0: edge-side CSR
    hist_side_kernel<<<hb, 256>>>(ei, p_ei32, p_re, p_ecnt, nnz);
    bsums_side_kernel<<<NB_E, 512>>>(p_ecnt, N_EDGES_C, p_bse);
    scanmid_side_kernel<<<1, 512>>>(p_bse, NB_E);
    apply_side_kernel<<<NB_E, 512>>>(p_ecnt, N_EDGES_C, p_bse, p_eoff, p_binv);
    fill_side_kernel<<<hb, 256>>>(p_ei32, p_re, p_eoff, ni, p_emem, nnz);

    // ---- joins + gathers
    cudaStreamWaitEvent(0, ev_gemm, 0);   // gather1 needs xw
    gather128h<<<blocks_e, 256>>>(p_xw, p_ef, p_emem, p_eoff, p_binv, N_EDGES_C);

    cudaStreamWaitEvent(0, ev_ncsr, 0);   // gather2 needs node CSR
    gather128h_w2<<<blocks_n, 256>>>(p_ef, p_nmem, p_noff, p_dinv, b1, W2, p_hw, N_NODES_C);

    // layer 2
    gather16<<<blocks_e, 256>>>(p_hw,  p_ef2, p_emem, p_eoff, p_binv, nullptr, N_EDGES_C);
    gather16<<<blocks_n, 256>>>(p_ef2, out,   p_nmem, p_noff, p_dinv, b2,      N_NODES_C);
}